// round 12
// baseline (speedup 1.0000x reference)
#include <cuda_runtime.h>
#include <cstdint>
#include <cmath>

// ---------------------------------------------------------------- constants
#define BB   2
#define TT   2048
#define CC   1024
#define NH   16
#define HD   64
#define BT   (BB*TT)          // 4096
#define C3   (3*CC)           // 3072
#define SCALE 0.125f

// ---------------------------------------------------------------- scratch
__device__ float g_qkv[(size_t)BT * C3];        // Q,K regions (cols<2048), col-permuted
__device__ float g_vt [(size_t)BB*NH*HD*TT];    // V transposed [b,h,d,token], tok pos_v-permuted
__device__ float g_y  [(size_t)BT * CC];        // attention out, col-permuted, tf32
__device__ float g_xp [(size_t)BT * CC];        // x rounded+col-permuted
__device__ float g_waT[(size_t)C3 * CC];        // w_attn^T [N,K], K-permuted, tf32
__device__ float g_wpT[(size_t)CC * CC];        // w_proj^T [N,K], K-permuted, tf32

// ---------------------------------------------------------------- utils
__device__ __forceinline__ uint32_t smem_u32(const void* p) {
    uint32_t a;
    asm("{ .reg .u64 t; cvta.to.shared.u64 t, %1; cvt.u32.u64 %0, t; }" : "=r"(a) : "l"(p));
    return a;
}
__device__ __forceinline__ float rn_tf32(float x) {
    uint32_t r;
    asm("cvt.rna.tf32.f32 %0, %1;" : "=r"(r) : "f"(x));
    return __uint_as_float(r);
}
#define CP_ASYNC16(dst, src) \
    asm volatile("cp.async.cg.shared.global [%0], [%1], 16;\n" :: "r"(dst), "l"(src))
#define CP_COMMIT() asm volatile("cp.async.commit_group;" ::: "memory")
#define CP_WAIT(n)  asm volatile("cp.async.wait_group %0;" :: "n"(n) : "memory")

__device__ __forceinline__ void mma_tf32(float* c, const uint32_t* a, const uint32_t* b) {
    asm volatile(
        "mma.sync.aligned.m16n8k8.row.col.f32.tf32.tf32.f32 "
        "{%0,%1,%2,%3}, {%4,%5,%6,%7}, {%8,%9}, {%0,%1,%2,%3};"
        : "+f"(c[0]), "+f"(c[1]), "+f"(c[2]), "+f"(c[3])
        : "r"(a[0]), "r"(a[1]), "r"(a[2]), "r"(a[3]), "r"(b[0]), "r"(b[1]));
}
__device__ __forceinline__ void ldsm_x4(uint32_t* r, uint32_t addr) {
    asm volatile("ldmatrix.sync.aligned.m8n8.x4.shared.b16 {%0,%1,%2,%3}, [%4];"
        : "=r"(r[0]), "=r"(r[1]), "=r"(r[2]), "=r"(r[3]) : "r"(addr));
}
// position of natural index u within its 8-group under gather [0,4,1,5,2,6,3,7]
__device__ __forceinline__ int perm8(int u) { return u < 4 ? 2 * u : 2 * u - 7; }
// V-token permutation: position of natural u under gather_v [0,2,4,6,1,3,5,7]
__device__ __forceinline__ int posv(int u) { return (u >> 1) + (u & 1) * 4; }

// ---------------------------------------------------------------- prep
__global__ void round_perm_kernel(const float* __restrict__ in, float* __restrict__ out) {
    size_t i = ((size_t)blockIdx.x * blockDim.x + threadIdx.x) * 8;
    float4 a = *(const float4*)(in + i);
    float4 b = *(const float4*)(in + i + 4);
    float4 o0 = make_float4(rn_tf32(a.x), rn_tf32(b.x), rn_tf32(a.y), rn_tf32(b.y));
    float4 o1 = make_float4(rn_tf32(a.z), rn_tf32(b.z), rn_tf32(a.w), rn_tf32(b.w));
    *(float4*)(out + i)     = o0;
    *(float4*)(out + i + 4) = o1;
}

__global__ void transpose_perm_kernel(const float* __restrict__ in, float* __restrict__ out,
                                      int K, int N) {
    __shared__ float tsm[32][33];
    int k0 = blockIdx.y * 32, n0 = blockIdx.x * 32;
    int tx = threadIdx.x, ty = threadIdx.y;     // 32 x 8
#pragma unroll
    for (int i = 0; i < 32; i += 8)
        tsm[ty + i][tx] = in[(size_t)(k0 + ty + i) * N + n0 + tx];
    __syncthreads();
    int kk = (tx & ~7) | (((tx & 7) >> 1) + (tx & 1) * 4);   // gather
#pragma unroll
    for (int i = 0; i < 32; i += 8)
        out[(size_t)(n0 + ty + i) * K + k0 + tx] = rn_tf32(tsm[kk][ty + i]);
}

// ---------------------------------------------------------------- tf32 GEMM (unchanged)
#define GBM 128
#define GBN 128
#define GBK 32
#define GSTG 3
#define TILE32 (128 * 32)
#define GEMM_SMEM (GSTG * 2 * TILE32 * 4)    // 98304 B

__global__ __launch_bounds__(256, 2) void gemm_tf32(
    const float* __restrict__ A, const float* __restrict__ Bt,
    const float* __restrict__ bias, float* __restrict__ C,
    float* __restrict__ vt, int M, int N, int K, int mode)
{
    extern __shared__ float smf[];
    float* As = smf;
    float* Bs = smf + GSTG * TILE32;

    const int tid = threadIdx.x, wid = tid >> 5, lane = tid & 31;
    const int g = lane >> 2, t = lane & 3;
    const int wm = wid & 3, wn = wid >> 2;
    const int m0 = blockIdx.y * GBM, n0 = blockIdx.x * GBN;
    const int NCH = K / GBK;

    uint32_t soff[4], agf[4], bgf[4];
#pragma unroll
    for (int i = 0; i < 4; i++) {
        int idx = tid + i * 256, row = idx >> 3, c4 = idx & 7;
        soff[i] = (uint32_t)(row * 32 + ((c4 * 4) ^ (4 * (row & 7)))) * 4u;
        agf[i]  = (uint32_t)((m0 + row) * K + c4 * 4);
        bgf[i]  = (uint32_t)((n0 + row) * K + c4 * 4);
    }
    const uint32_t asb0 = smem_u32(As), bsb0 = smem_u32(Bs);
    int s_fill = 0;

    const int lq = lane >> 3, li = lane & 7;
    const uint32_t sw4 = 4u * (uint32_t)li;
    const uint32_t ko  = (uint32_t)((lq >> 1) * 4);
    uint32_t a_rb[2], b_rb[4];
#pragma unroll
    for (int mt = 0; mt < 2; mt++)
        a_rb[mt] = (uint32_t)(wm * 32 + mt * 16 + (lq & 1) * 8 + li) * 128u;
#pragma unroll
    for (int p = 0; p < 4; p++)
        b_rb[p] = (uint32_t)(wn * 64 + p * 16 + (lq & 1) * 8 + li) * 128u;

    float acc[2][8][4];
#pragma unroll
    for (int mt = 0; mt < 2; mt++)
#pragma unroll
        for (int nt = 0; nt < 8; nt++)
#pragma unroll
            for (int k = 0; k < 4; k++) acc[mt][nt][k] = 0.f;

#pragma unroll
    for (int s = 0; s < GSTG - 1; s++) {
        uint32_t ab = asb0 + s_fill * (TILE32 * 4), bb = bsb0 + s_fill * (TILE32 * 4);
#pragma unroll
        for (int i = 0; i < 4; i++) {
            CP_ASYNC16(ab + soff[i], A  + agf[i]);
            CP_ASYNC16(bb + soff[i], Bt + bgf[i]);
        }
#pragma unroll
        for (int i = 0; i < 4; i++) { agf[i] += GBK; bgf[i] += GBK; }
        if (++s_fill == GSTG) s_fill = 0;
        CP_COMMIT();
    }

    int s_use = 0;
    for (int kb = 0; kb < NCH; kb++) {
        CP_WAIT(GSTG - 2);
        __syncthreads();

        if (kb + GSTG - 1 < NCH) {
            uint32_t ab = asb0 + s_fill * (TILE32 * 4), bb = bsb0 + s_fill * (TILE32 * 4);
#pragma unroll
            for (int i = 0; i < 4; i++) {
                CP_ASYNC16(ab + soff[i], A  + agf[i]);
                CP_ASYNC16(bb + soff[i], Bt + bgf[i]);
            }
#pragma unroll
            for (int i = 0; i < 4; i++) { agf[i] += GBK; bgf[i] += GBK; }
            if (++s_fill == GSTG) s_fill = 0;
        }
        CP_COMMIT();

        const uint32_t asb = asb0 + s_use * (TILE32 * 4);
        const uint32_t bsb = bsb0 + s_use * (TILE32 * 4);
        if (++s_use == GSTG) s_use = 0;
#pragma unroll
        for (int ks = 0; ks < 4; ks++) {
            const uint32_t kx = (((uint32_t)(ks * 8) + ko) ^ sw4) * 4u;
            uint32_t af[2][4], bf[8][2], bt4[4];
            ldsm_x4(af[0], asb + a_rb[0] + kx);
            ldsm_x4(af[1], asb + a_rb[1] + kx);
#pragma unroll
            for (int p = 0; p < 4; p++) {
                ldsm_x4(bt4, bsb + b_rb[p] + kx);
                bf[2 * p][0]     = bt4[0];
                bf[2 * p + 1][0] = bt4[1];
                bf[2 * p][1]     = bt4[2];
                bf[2 * p + 1][1] = bt4[3];
            }
#pragma unroll
            for (int mt = 0; mt < 2; mt++)
#pragma unroll
                for (int nt = 0; nt < 8; nt++)
                    mma_tf32(acc[mt][nt], af[mt], bf[nt]);
        }
    }

#pragma unroll
    for (int mt = 0; mt < 2; mt++) {
        int r0 = m0 + wm * 32 + mt * 16 + g;
#pragma unroll
        for (int nt = 0; nt < 8; nt++) {
            int c = n0 + wn * 64 + nt * 8 + 2 * t;
            float2 b2 = *(const float2*)(bias + c);
            float2 v0 = make_float2(acc[mt][nt][0] + b2.x, acc[mt][nt][1] + b2.y);
            float2 v1 = make_float2(acc[mt][nt][2] + b2.x, acc[mt][nt][3] + b2.y);
            if (mode == 1) {
                v0.x = rn_tf32(v0.x); v0.y = rn_tf32(v0.y);
                v1.x = rn_tf32(v1.x); v1.y = rn_tf32(v1.y);
                if (c < 2048) {
                    int c0p = (c & ~7) | perm8(c & 7);
                    int c1p = (c & ~7) | perm8((c & 7) + 1);
                    C[(size_t)r0 * N + c0p] = v0.x;
                    C[(size_t)r0 * N + c1p] = v0.y;
                    C[(size_t)(r0 + 8) * N + c0p] = v1.x;
                    C[(size_t)(r0 + 8) * N + c1p] = v1.y;
                } else {
                    int h  = (c - 2048) >> 6;
                    int d0 = (c - 2048) & 63;
                    int b0  = r0 >> 11;
                    int tp0 = ((r0 & 2047) & ~7) | posv(r0 & 7);
                    int tp1 = (((r0 + 8) & 2047) & ~7) | posv((r0 + 8) & 7);
                    float* vb = vt + ((size_t)(b0 * NH + h) * HD + d0) * TT;
                    vb[tp0]      = v0.x;
                    vb[TT + tp0] = v0.y;
                    vb[tp1]      = v1.x;
                    vb[TT + tp1] = v1.y;
                }
            } else {
                *(float2*)(C + (size_t)r0 * N + c) = v0;
                *(float2*)(C + (size_t)(r0 + 8) * N + c) = v1;
            }
        }
    }
}

// ---------------------------------------------------------------- attention
// AQ=128: 256 threads / 8 warps, each warp owns 16 Q rows. One K/V tile
// feeds 128 Q rows -> staging/barrier overhead per work unit halves.
// P stays in registers (accumulator == A frag with pos_v-permuted V tokens).
#define AQ 128
#define AK 64
#define SM_QS 0
#define SM_KS 8192
#define SM_VS (SM_KS + 2*4096)
#define ATTN_SMEM ((SM_VS + 2*4096) * 4)     // 98304 B

__global__ __launch_bounds__(256, 2) void attn_tc(const float* __restrict__ qkv,
                                                  const float* __restrict__ vt,
                                                  float* __restrict__ y)
{
    extern __shared__ float sm[];
    const int tid = threadIdx.x;
    const int wid = tid >> 5, lane = tid & 31;
    const int g = lane >> 2, t = lane & 3;
    const int qtp = gridDim.x - 1 - blockIdx.x;    // longest blocks first
    const int h  = blockIdx.y;
    const int b  = blockIdx.z;
    const int q0 = qtp * AQ;
    const int r0 = wid * 16 + g;                   // local Q row of c0/c1
    const int nkt = 2 * qtp + 2;                   // K tiles to process
    const uint32_t smb = smem_u32(sm);

    // ldmatrix lane geometry
    const int lq = lane >> 3, li = lane & 7;
    const uint32_t sw4 = 4u * (uint32_t)li;
    const uint32_t ko  = (uint32_t)((lq >> 1) * 4);
    const uint32_t rq  = (uint32_t)((lq & 1) * 8 + li);
    const uint32_t q_rb = (uint32_t)(wid * 16 + rq) * 256u;
    uint32_t n_rb[4];
#pragma unroll
    for (int p = 0; p < 4; p++) n_rb[p] = (uint32_t)(p * 16 + rq) * 256u;

    // hoisted staging geometry (K/V: 64x64 tile, 256 threads -> 4 iters)
    uint32_t st_off[4], kg[4], vg[4];
#pragma unroll
    for (int i = 0; i < 4; i++) {
        int idx = tid + i * 256, row = idx >> 4, c4 = idx & 15;
        st_off[i] = (uint32_t)(row * 64 + ((c4 * 4) ^ (4 * (row & 7)))) * 4u;
        kg[i] = (uint32_t)(row * C3 + c4 * 4);
        vg[i] = (uint32_t)(row * TT + c4 * 4);
    }
    const float* kb0 = qkv + ((size_t)(b * TT)) * C3 + CC + h * HD;
    const float* vb0 = vt + ((size_t)(b * NH + h) * HD) * TT;

    // stage Q (128 rows, scaled, swizzled)
    {
        const float* qbase = qkv + ((size_t)(b * TT + q0)) * C3 + h * HD;
#pragma unroll
        for (int i = 0; i < 8; i++) {
            int idx = tid + i * 256, row = idx >> 4, c4 = idx & 15;
            float4 v = *(const float4*)(qbase + (size_t)row * C3 + c4 * 4);
            v.x *= SCALE; v.y *= SCALE; v.z *= SCALE; v.w *= SCALE;
            *(float4*)(&sm[SM_QS + row * 64 + ((c4 * 4) ^ (4 * (row & 7)))]) = v;
        }
    }
    // prologue K/V tile 0
    {
        uint32_t kd = smb + SM_KS * 4, vd = smb + SM_VS * 4;
#pragma unroll
        for (int i = 0; i < 4; i++) {
            CP_ASYNC16(kd + st_off[i], kb0 + kg[i]);
            CP_ASYNC16(vd + st_off[i], vb0 + vg[i]);
        }
    }
    CP_COMMIT();
    __syncthreads();

    // Q fragments once
    uint32_t qf[8][4];
#pragma unroll
    for (int ds = 0; ds < 8; ds++)
        ldsm_x4(qf[ds], smb + SM_QS * 4 + q_rb + ((((uint32_t)(ds * 8) + ko) ^ sw4) << 2));

    float oacc[8][4];
#pragma unroll
    for (int nt = 0; nt < 8; nt++)
#pragma unroll
        for (int k = 0; k < 4; k++) oacc[nt][k] = 0.f;
    float mrow0 = -INFINITY, mrow1 = -INFINITY, lrow0 = 0.f, lrow1 = 0.f;

    const int pp0 = perm8(2 * t), pp1 = perm8(2 * t + 1);

    for (int kt = 0; kt < nkt; kt++) {
        const int buf = kt & 1;
        CP_WAIT(0);
        __syncthreads();
        if (kt + 1 < nkt) {
            uint32_t kd = smb + (SM_KS + (buf ^ 1) * 4096) * 4;
            uint32_t vd = smb + (SM_VS + (buf ^ 1) * 4096) * 4;
            const float* kp = kb0 + (size_t)(kt + 1) * 64 * C3;
            const float* vp = vb0 + (kt + 1) * 64;
#pragma unroll
            for (int i = 0; i < 4; i++) {
                CP_ASYNC16(kd + st_off[i], kp + kg[i]);
                CP_ASYNC16(vd + st_off[i], vp + vg[i]);
            }
        }
        CP_COMMIT();

        const uint32_t ksb = smb + (SM_KS + buf * 4096) * 4;
        const uint32_t vsb = smb + (SM_VS + buf * 4096) * 4;

        // S = Q K^T
        float sacc[8][4];
#pragma unroll
        for (int nt = 0; nt < 8; nt++)
#pragma unroll
            for (int k = 0; k < 4; k++) sacc[nt][k] = 0.f;
#pragma unroll
        for (int ds = 0; ds < 8; ds++) {
            const uint32_t kx = (((uint32_t)(ds * 8) + ko) ^ sw4) << 2;
            uint32_t bf[8][2], bt4[4];
#pragma unroll
            for (int p = 0; p < 4; p++) {
                ldsm_x4(bt4, ksb + n_rb[p] + kx);
                bf[2 * p][0]     = bt4[0];
                bf[2 * p + 1][0] = bt4[1];
                bf[2 * p][1]     = bt4[2];
                bf[2 * p + 1][1] = bt4[3];
            }
#pragma unroll
            for (int nt = 0; nt < 8; nt++)
                mma_tf32(sacc[nt], qf[ds], bf[nt]);
        }

        // causal mask (global indices; guard conservative on smaller row r0)
        if (kt * 64 + 63 > r0) {       // tile not fully below diagonal
            const int gr0 = r0, gr1 = r0 + 8;      // local rows; cols local too
            const int cb0 = kt * 64 - 0;           // tile col base relative to q0? no:
            // global row = q0 + local_row; global col = kt*64 + c_local.
            // mask iff kt*64 + c_local > q0 + local_row  <=>  c_local + kt*64 - q0 > local_row
            const int shift = kt * 64 - q0;
#pragma unroll
            for (int nt = 0; nt < 8; nt++) {
                int c = nt * 8 + 2 * t + shift;
                if (c     > gr0) sacc[nt][0] = -1e30f;
                if (c + 1 > gr0) sacc[nt][1] = -1e30f;
                if (c     > gr1) sacc[nt][2] = -1e30f;
                if (c + 1 > gr1) sacc[nt][3] = -1e30f;
            }
        }

        // online softmax
        float tm0 = -INFINITY, tm1 = -INFINITY;
#pragma unroll
        for (int nt = 0; nt < 8; nt++) {
            tm0 = fmaxf(tm0, fmaxf(sacc[nt][0], sacc[nt][1]));
            tm1 = fmaxf(tm1, fmaxf(sacc[nt][2], sacc[nt][3]));
        }
        tm0 = fmaxf(tm0, __shfl_xor_sync(0xffffffffu, tm0, 1));
        tm0 = fmaxf(tm0, __shfl_xor_sync(0xffffffffu, tm0, 2));
        tm1 = fmaxf(tm1, __shfl_xor_sync(0xffffffffu, tm1, 1));
        tm1 = fmaxf(tm1, __shfl_xor_sync(0xffffffffu, tm1, 2));
        float m0 = fmaxf(mrow0, tm0), m1 = fmaxf(mrow1, tm1);
        float a0 = __expf(mrow0 - m0), a1 = __expf(mrow1 - m1);
        mrow0 = m0; mrow1 = m1;
        float rs0 = 0.f, rs1 = 0.f;
#pragma unroll
        for (int nt = 0; nt < 8; nt++) {
            sacc[nt][0] = __expf(sacc[nt][0] - m0); rs0 += sacc[nt][0];
            sacc[nt][1] = __expf(sacc[nt][1] - m0); rs0 += sacc[nt][1];
            sacc[nt][2] = __expf(sacc[nt][2] - m1); rs1 += sacc[nt][2];
            sacc[nt][3] = __expf(sacc[nt][3] - m1); rs1 += sacc[nt][3];
        }
        rs0 += __shfl_xor_sync(0xffffffffu, rs0, 1);
        rs0 += __shfl_xor_sync(0xffffffffu, rs0, 2);
        rs1 += __shfl_xor_sync(0xffffffffu, rs1, 1);
        rs1 += __shfl_xor_sync(0xffffffffu, rs1, 2);
        lrow0 = lrow0 * a0 + rs0;
        lrow1 = lrow1 * a1 + rs1;
#pragma unroll
        for (int nt = 0; nt < 8; nt++) {
            oacc[nt][0] *= a0; oacc[nt][1] *= a0;
            oacc[nt][2] *= a1; oacc[nt][3] *= a1;
        }

        // O += P @ V — P from sacc registers ([c0,c2,c1,c3], pos_v V tokens)
#pragma unroll
        for (int kk = 0; kk < 8; kk++) {
            const uint32_t kx = (((uint32_t)(kk * 8) + ko) ^ sw4) << 2;
            uint32_t af[4], bf[8][2], bt4[4];
            af[0] = __float_as_uint(rn_tf32(sacc[kk][0]));
            af[1] = __float_as_uint(rn_tf32(sacc[kk][2]));
            af[2] = __float_as_uint(rn_tf32(sacc[kk][1]));
            af[3] = __float_as_uint(rn_tf32(sacc[kk][3]));
#pragma unroll
            for (int p = 0; p < 4; p++) {
                ldsm_x4(bt4, vsb + n_rb[p] + kx);
                bf[2 * p][0]     = bt4[0];
                bf[2 * p + 1][0] = bt4[1];
                bf[2 * p][1]     = bt4[2];
                bf[2 * p + 1][1] = bt4[3];
            }
#pragma unroll
            for (int nt = 0; nt < 8; nt++)
                mma_tf32(oacc[nt], af, bf[nt]);
        }
    }

    // normalize + store, col-permuted (feeds proj GEMM's permuted A)
    float inv0 = 1.0f / lrow0, inv1 = 1.0f / lrow1;
    float* ybase = y + ((size_t)(b * TT + q0)) * CC + h * HD;
#pragma unroll
    for (int nt = 0; nt < 8; nt++) {
        int cb = nt * 8;
        ybase[(size_t)r0 * CC + cb + pp0]       = rn_tf32(oacc[nt][0] * inv0);
        ybase[(size_t)r0 * CC + cb + pp1]       = rn_tf32(oacc[nt][1] * inv0);
        ybase[(size_t)(r0 + 8) * CC + cb + pp0] = rn_tf32(oacc[nt][2] * inv1);
        ybase[(size_t)(r0 + 8) * CC + cb + pp1] = rn_tf32(oacc[nt][3] * inv1);
    }
}

// ---------------------------------------------------------------- launch
extern "C" void kernel_launch(void* const* d_in, const int* in_sizes, int n_in,
                              void* d_out, int out_size)
{
    const float* x      = (const float*)d_in[0];
    const float* w_attn = (const float*)d_in[1];
    const float* b_attn = (const float*)d_in[2];
    const float* w_proj = (const float*)d_in[3];
    const float* b_proj = (const float*)d_in[4];
    float* out = (float*)d_out;

    float *qkv, *vt, *yb, *xp, *waT, *wpT;
    cudaGetSymbolAddress((void**)&qkv, g_qkv);
    cudaGetSymbolAddress((void**)&vt,  g_vt);
    cudaGetSymbolAddress((void**)&yb,  g_y);
    cudaGetSymbolAddress((void**)&xp,  g_xp);
    cudaGetSymbolAddress((void**)&waT, g_waT);
    cudaGetSymbolAddress((void**)&wpT, g_wpT);

    cudaFuncSetAttribute(gemm_tf32, cudaFuncAttributeMaxDynamicSharedMemorySize, GEMM_SMEM);
    cudaFuncSetAttribute(attn_tc,   cudaFuncAttributeMaxDynamicSharedMemorySize, ATTN_SMEM);

    round_perm_kernel<<<(BT * CC) / (256 * 8), 256>>>(x, xp);
    transpose_perm_kernel<<<dim3(C3 / 32, CC / 32), dim3(32, 8)>>>(w_attn, waT, CC, C3);
    transpose_perm_kernel<<<dim3(CC / 32, CC / 32), dim3(32, 8)>>>(w_proj, wpT, CC, CC);

    gemm_tf32<<<dim3(C3 / GBN, BT / GBM), 256, GEMM_SMEM>>>(xp, waT, b_attn, qkv, vt,
                                                            BT, C3, CC, 1);

    attn_tc<<<dim3(TT / AQ, NH, BB), 256, ATTN_SMEM>>>(qkv, vt, yb);

    gemm_tf32<<<dim3(CC / GBN, BT / GBM), 256, GEMM_SMEM>>>(yb, wpT, b_proj, out, vt,
                                                            BT, CC, CC, 0);
}

// round 13
// speedup vs baseline: 1.1595x; 1.1595x over previous
#include <cuda_runtime.h>
#include <cstdint>
#include <cmath>

// ---------------------------------------------------------------- constants
#define BB   2
#define TT   2048
#define CC   1024
#define NH   16
#define HD   64
#define BT   (BB*TT)          // 4096
#define C3   (3*CC)           // 3072
#define SCALE 0.125f

// ---------------------------------------------------------------- scratch
__device__ float g_qkv[(size_t)BT * C3];        // Q,K regions (cols<2048), col-permuted
__device__ float g_vt [(size_t)BB*NH*HD*TT];    // V transposed [b,h,d,token], tok pos_v-permuted
__device__ float g_y  [(size_t)BT * CC];        // attention out, col-permuted, tf32
__device__ float g_xp [(size_t)BT * CC];        // x rounded+col-permuted
__device__ float g_waT[(size_t)C3 * CC];        // w_attn^T [N,K], K-permuted, tf32
__device__ float g_wpT[(size_t)CC * CC];        // w_proj^T [N,K], K-permuted, tf32

// ---------------------------------------------------------------- utils
__device__ __forceinline__ uint32_t smem_u32(const void* p) {
    uint32_t a;
    asm("{ .reg .u64 t; cvta.to.shared.u64 t, %1; cvt.u32.u64 %0, t; }" : "=r"(a) : "l"(p));
    return a;
}
__device__ __forceinline__ float rn_tf32(float x) {
    uint32_t r;
    asm("cvt.rna.tf32.f32 %0, %1;" : "=r"(r) : "f"(x));
    return __uint_as_float(r);
}
#define CP_ASYNC16(dst, src) \
    asm volatile("cp.async.cg.shared.global [%0], [%1], 16;\n" :: "r"(dst), "l"(src))
#define CP_COMMIT() asm volatile("cp.async.commit_group;" ::: "memory")
#define CP_WAIT(n)  asm volatile("cp.async.wait_group %0;" :: "n"(n) : "memory")

__device__ __forceinline__ void mma_tf32(float* c, const uint32_t* a, const uint32_t* b) {
    asm volatile(
        "mma.sync.aligned.m16n8k8.row.col.f32.tf32.tf32.f32 "
        "{%0,%1,%2,%3}, {%4,%5,%6,%7}, {%8,%9}, {%0,%1,%2,%3};"
        : "+f"(c[0]), "+f"(c[1]), "+f"(c[2]), "+f"(c[3])
        : "r"(a[0]), "r"(a[1]), "r"(a[2]), "r"(a[3]), "r"(b[0]), "r"(b[1]));
}
__device__ __forceinline__ void ldsm_x4(uint32_t* r, uint32_t addr) {
    asm volatile("ldmatrix.sync.aligned.m8n8.x4.shared.b16 {%0,%1,%2,%3}, [%4];"
        : "=r"(r[0]), "=r"(r[1]), "=r"(r[2]), "=r"(r[3]) : "r"(addr));
}
// position of natural index u within its 8-group under gather [0,4,1,5,2,6,3,7]
__device__ __forceinline__ int perm8(int u) { return u < 4 ? 2 * u : 2 * u - 7; }
// V-token permutation: position of natural u under gather_v [0,2,4,6,1,3,5,7]
__device__ __forceinline__ int posv(int u) { return (u >> 1) + (u & 1) * 4; }

// ---------------------------------------------------------------- prep
__global__ void round_perm_kernel(const float* __restrict__ in, float* __restrict__ out) {
    size_t i = ((size_t)blockIdx.x * blockDim.x + threadIdx.x) * 8;
    float4 a = *(const float4*)(in + i);
    float4 b = *(const float4*)(in + i + 4);
    float4 o0 = make_float4(rn_tf32(a.x), rn_tf32(b.x), rn_tf32(a.y), rn_tf32(b.y));
    float4 o1 = make_float4(rn_tf32(a.z), rn_tf32(b.z), rn_tf32(a.w), rn_tf32(b.w));
    *(float4*)(out + i)     = o0;
    *(float4*)(out + i + 4) = o1;
}

__global__ void transpose_perm_kernel(const float* __restrict__ in, float* __restrict__ out,
                                      int K, int N) {
    __shared__ float tsm[32][33];
    int k0 = blockIdx.y * 32, n0 = blockIdx.x * 32;
    int tx = threadIdx.x, ty = threadIdx.y;     // 32 x 8
#pragma unroll
    for (int i = 0; i < 32; i += 8)
        tsm[ty + i][tx] = in[(size_t)(k0 + ty + i) * N + n0 + tx];
    __syncthreads();
    int kk = (tx & ~7) | (((tx & 7) >> 1) + (tx & 1) * 4);   // gather
#pragma unroll
    for (int i = 0; i < 32; i += 8)
        out[(size_t)(n0 + ty + i) * K + k0 + tx] = rn_tf32(tsm[kk][ty + i]);
}

// ---------------------------------------------------------------- tf32 GEMM (unchanged)
#define GBM 128
#define GBN 128
#define GBK 32
#define GSTG 3
#define TILE32 (128 * 32)
#define GEMM_SMEM (GSTG * 2 * TILE32 * 4)    // 98304 B

__global__ __launch_bounds__(256, 2) void gemm_tf32(
    const float* __restrict__ A, const float* __restrict__ Bt,
    const float* __restrict__ bias, float* __restrict__ C,
    float* __restrict__ vt, int M, int N, int K, int mode)
{
    extern __shared__ float smf[];
    float* As = smf;
    float* Bs = smf + GSTG * TILE32;

    const int tid = threadIdx.x, wid = tid >> 5, lane = tid & 31;
    const int g = lane >> 2, t = lane & 3;
    const int wm = wid & 3, wn = wid >> 2;
    const int m0 = blockIdx.y * GBM, n0 = blockIdx.x * GBN;
    const int NCH = K / GBK;

    uint32_t soff[4], agf[4], bgf[4];
#pragma unroll
    for (int i = 0; i < 4; i++) {
        int idx = tid + i * 256, row = idx >> 3, c4 = idx & 7;
        soff[i] = (uint32_t)(row * 32 + ((c4 * 4) ^ (4 * (row & 7)))) * 4u;
        agf[i]  = (uint32_t)((m0 + row) * K + c4 * 4);
        bgf[i]  = (uint32_t)((n0 + row) * K + c4 * 4);
    }
    const uint32_t asb0 = smem_u32(As), bsb0 = smem_u32(Bs);
    int s_fill = 0;

    const int lq = lane >> 3, li = lane & 7;
    const uint32_t sw4 = 4u * (uint32_t)li;
    const uint32_t ko  = (uint32_t)((lq >> 1) * 4);
    uint32_t a_rb[2], b_rb[4];
#pragma unroll
    for (int mt = 0; mt < 2; mt++)
        a_rb[mt] = (uint32_t)(wm * 32 + mt * 16 + (lq & 1) * 8 + li) * 128u;
#pragma unroll
    for (int p = 0; p < 4; p++)
        b_rb[p] = (uint32_t)(wn * 64 + p * 16 + (lq & 1) * 8 + li) * 128u;

    float acc[2][8][4];
#pragma unroll
    for (int mt = 0; mt < 2; mt++)
#pragma unroll
        for (int nt = 0; nt < 8; nt++)
#pragma unroll
            for (int k = 0; k < 4; k++) acc[mt][nt][k] = 0.f;

#pragma unroll
    for (int s = 0; s < GSTG - 1; s++) {
        uint32_t ab = asb0 + s_fill * (TILE32 * 4), bb = bsb0 + s_fill * (TILE32 * 4);
#pragma unroll
        for (int i = 0; i < 4; i++) {
            CP_ASYNC16(ab + soff[i], A  + agf[i]);
            CP_ASYNC16(bb + soff[i], Bt + bgf[i]);
        }
#pragma unroll
        for (int i = 0; i < 4; i++) { agf[i] += GBK; bgf[i] += GBK; }
        if (++s_fill == GSTG) s_fill = 0;
        CP_COMMIT();
    }

    int s_use = 0;
    for (int kb = 0; kb < NCH; kb++) {
        CP_WAIT(GSTG - 2);
        __syncthreads();

        if (kb + GSTG - 1 < NCH) {
            uint32_t ab = asb0 + s_fill * (TILE32 * 4), bb = bsb0 + s_fill * (TILE32 * 4);
#pragma unroll
            for (int i = 0; i < 4; i++) {
                CP_ASYNC16(ab + soff[i], A  + agf[i]);
                CP_ASYNC16(bb + soff[i], Bt + bgf[i]);
            }
#pragma unroll
            for (int i = 0; i < 4; i++) { agf[i] += GBK; bgf[i] += GBK; }
            if (++s_fill == GSTG) s_fill = 0;
        }
        CP_COMMIT();

        const uint32_t asb = asb0 + s_use * (TILE32 * 4);
        const uint32_t bsb = bsb0 + s_use * (TILE32 * 4);
        if (++s_use == GSTG) s_use = 0;
#pragma unroll
        for (int ks = 0; ks < 4; ks++) {
            const uint32_t kx = (((uint32_t)(ks * 8) + ko) ^ sw4) * 4u;
            uint32_t af[2][4], bf[8][2], bt4[4];
            ldsm_x4(af[0], asb + a_rb[0] + kx);
            ldsm_x4(af[1], asb + a_rb[1] + kx);
#pragma unroll
            for (int p = 0; p < 4; p++) {
                ldsm_x4(bt4, bsb + b_rb[p] + kx);
                bf[2 * p][0]     = bt4[0];
                bf[2 * p + 1][0] = bt4[1];
                bf[2 * p][1]     = bt4[2];
                bf[2 * p + 1][1] = bt4[3];
            }
#pragma unroll
            for (int mt = 0; mt < 2; mt++)
#pragma unroll
                for (int nt = 0; nt < 8; nt++)
                    mma_tf32(acc[mt][nt], af[mt], bf[nt]);
        }
    }

#pragma unroll
    for (int mt = 0; mt < 2; mt++) {
        int r0 = m0 + wm * 32 + mt * 16 + g;
#pragma unroll
        for (int nt = 0; nt < 8; nt++) {
            int c = n0 + wn * 64 + nt * 8 + 2 * t;
            float2 b2 = *(const float2*)(bias + c);
            float2 v0 = make_float2(acc[mt][nt][0] + b2.x, acc[mt][nt][1] + b2.y);
            float2 v1 = make_float2(acc[mt][nt][2] + b2.x, acc[mt][nt][3] + b2.y);
            if (mode == 1) {
                v0.x = rn_tf32(v0.x); v0.y = rn_tf32(v0.y);
                v1.x = rn_tf32(v1.x); v1.y = rn_tf32(v1.y);
                if (c < 2048) {
                    int c0p = (c & ~7) | perm8(c & 7);
                    int c1p = (c & ~7) | perm8((c & 7) + 1);
                    C[(size_t)r0 * N + c0p] = v0.x;
                    C[(size_t)r0 * N + c1p] = v0.y;
                    C[(size_t)(r0 + 8) * N + c0p] = v1.x;
                    C[(size_t)(r0 + 8) * N + c1p] = v1.y;
                } else {
                    int h  = (c - 2048) >> 6;
                    int d0 = (c - 2048) & 63;
                    int b0  = r0 >> 11;
                    int tp0 = ((r0 & 2047) & ~7) | posv(r0 & 7);
                    int tp1 = (((r0 + 8) & 2047) & ~7) | posv((r0 + 8) & 7);
                    float* vb = vt + ((size_t)(b0 * NH + h) * HD + d0) * TT;
                    vb[tp0]      = v0.x;
                    vb[TT + tp0] = v0.y;
                    vb[tp1]      = v1.x;
                    vb[TT + tp1] = v1.y;
                }
            } else {
                *(float2*)(C + (size_t)r0 * N + c) = v0;
                *(float2*)(C + (size_t)(r0 + 8) * N + c) = v1;
            }
        }
    }
}

// ---------------------------------------------------------------- attention
// R11 structure (AQ=64, 128 threads) + smem reuse: the Q tile region is dead
// after the one-time Q-fragment ldmatrix, so V buffer 1 aliases it.
// smem 64KB -> 3 CTAs/SM (was 2).
#define AQ 64
#define AK 64
#define SM_QS 0                               // 4096 floats; reused as V buf 1
#define SM_KS 4096                            // two K bufs: 4096..12287
#define SM_VS 12288                           // V buf 0
#define ATTN_SMEM (16384 * 4)                 // 65536 B

__global__ __launch_bounds__(128, 3) void attn_tc(const float* __restrict__ qkv,
                                                  const float* __restrict__ vt,
                                                  float* __restrict__ y)
{
    extern __shared__ float sm[];
    const int tid = threadIdx.x;
    const int wid = tid >> 5, lane = tid & 31;
    const int g = lane >> 2, t = lane & 3;
    const int qt = gridDim.x - 1 - blockIdx.x;
    const int h  = blockIdx.y;
    const int b  = blockIdx.z;
    const int q0 = qt * AQ;
    const int r0 = wid * 16 + g;
    const uint32_t smb = smem_u32(sm);

    // ldmatrix lane geometry
    const int lq = lane >> 3, li = lane & 7;
    const uint32_t sw4 = 4u * (uint32_t)li;
    const uint32_t ko  = (uint32_t)((lq >> 1) * 4);
    const uint32_t rq  = (uint32_t)((lq & 1) * 8 + li);
    const uint32_t q_rb = (uint32_t)(wid * 16 + rq) * 256u;
    uint32_t n_rb[4];
#pragma unroll
    for (int p = 0; p < 4; p++) n_rb[p] = (uint32_t)(p * 16 + rq) * 256u;

    // V buffer bases: buf0 = SM_VS, buf1 = SM_QS (aliased over dead Q tile)
    const uint32_t v_base[2] = { smb + SM_VS * 4, smb + SM_QS * 4 };

    // hoisted staging geometry
    uint32_t st_off[8], kg[8], vg[8];
#pragma unroll
    for (int i = 0; i < 8; i++) {
        int idx = tid + i * 128, row = idx >> 4, c4 = idx & 15;
        st_off[i] = (uint32_t)(row * 64 + ((c4 * 4) ^ (4 * (row & 7)))) * 4u;
        kg[i] = (uint32_t)(row * C3 + c4 * 4);
        vg[i] = (uint32_t)(row * TT + c4 * 4);
    }
    const float* kb0 = qkv + ((size_t)(b * TT)) * C3 + CC + h * HD;
    const float* vb0 = vt + ((size_t)(b * NH + h) * HD) * TT;

    // stage Q (scaled, swizzled)
    {
        const float* qbase = qkv + ((size_t)(b * TT + q0)) * C3 + h * HD;
#pragma unroll
        for (int i = 0; i < 8; i++) {
            int idx = tid + i * 128, row = idx >> 4, c4 = idx & 15;
            float4 v = *(const float4*)(qbase + (size_t)row * C3 + c4 * 4);
            v.x *= SCALE; v.y *= SCALE; v.z *= SCALE; v.w *= SCALE;
            *(float4*)(&sm[SM_QS + row * 64 + ((c4 * 4) ^ (4 * (row & 7)))]) = v;
        }
    }
    // prologue K/V tile 0 (V0 in its own region; Q region untouched)
    {
        uint32_t kd = smb + SM_KS * 4, vd = v_base[0];
#pragma unroll
        for (int i = 0; i < 8; i++) {
            CP_ASYNC16(kd + st_off[i], kb0 + kg[i]);
            CP_ASYNC16(vd + st_off[i], vb0 + vg[i]);
        }
    }
    CP_COMMIT();
    __syncthreads();

    // Q fragments once (Q smem dead afterwards; V buf1 may overwrite it —
    // the first such write is the kt=0 prefetch, after the next barrier)
    uint32_t qf[8][4];
#pragma unroll
    for (int ds = 0; ds < 8; ds++)
        ldsm_x4(qf[ds], smb + SM_QS * 4 + q_rb + ((((uint32_t)(ds * 8) + ko) ^ sw4) << 2));

    float oacc[8][4];
#pragma unroll
    for (int nt = 0; nt < 8; nt++)
#pragma unroll
        for (int k = 0; k < 4; k++) oacc[nt][k] = 0.f;
    float mrow0 = -INFINITY, mrow1 = -INFINITY, lrow0 = 0.f, lrow1 = 0.f;

    const int pp0 = perm8(2 * t), pp1 = perm8(2 * t + 1);

    for (int kt = 0; kt <= qt; kt++) {
        const int buf = kt & 1;
        CP_WAIT(0);
        __syncthreads();
        if (kt < qt) {
            uint32_t kd = smb + (SM_KS + (buf ^ 1) * 4096) * 4;
            uint32_t vd = v_base[buf ^ 1];
            const float* kp = kb0 + (size_t)(kt + 1) * 64 * C3;
            const float* vp = vb0 + (kt + 1) * 64;
#pragma unroll
            for (int i = 0; i < 8; i++) {
                CP_ASYNC16(kd + st_off[i], kp + kg[i]);
                CP_ASYNC16(vd + st_off[i], vp + vg[i]);
            }
        }
        CP_COMMIT();

        const uint32_t ksb = smb + (SM_KS + buf * 4096) * 4;
        const uint32_t vsb = v_base[buf];

        // S = Q K^T
        float sacc[8][4];
#pragma unroll
        for (int nt = 0; nt < 8; nt++)
#pragma unroll
            for (int k = 0; k < 4; k++) sacc[nt][k] = 0.f;
#pragma unroll
        for (int ds = 0; ds < 8; ds++) {
            const uint32_t kx = (((uint32_t)(ds * 8) + ko) ^ sw4) << 2;
            uint32_t bf[8][2], bt4[4];
#pragma unroll
            for (int p = 0; p < 4; p++) {
                ldsm_x4(bt4, ksb + n_rb[p] + kx);
                bf[2 * p][0]     = bt4[0];
                bf[2 * p + 1][0] = bt4[1];
                bf[2 * p][1]     = bt4[2];
                bf[2 * p + 1][1] = bt4[3];
            }
#pragma unroll
            for (int nt = 0; nt < 8; nt++)
                mma_tf32(sacc[nt], qf[ds], bf[nt]);
        }

        if (kt == qt) {
#pragma unroll
            for (int nt = 0; nt < 8; nt++) {
                int c = nt * 8 + 2 * t;
                if (c     > r0)     sacc[nt][0] = -1e30f;
                if (c + 1 > r0)     sacc[nt][1] = -1e30f;
                if (c     > r0 + 8) sacc[nt][2] = -1e30f;
                if (c + 1 > r0 + 8) sacc[nt][3] = -1e30f;
            }
        }

        // online softmax
        float tm0 = -INFINITY, tm1 = -INFINITY;
#pragma unroll
        for (int nt = 0; nt < 8; nt++) {
            tm0 = fmaxf(tm0, fmaxf(sacc[nt][0], sacc[nt][1]));
            tm1 = fmaxf(tm1, fmaxf(sacc[nt][2], sacc[nt][3]));
        }
        tm0 = fmaxf(tm0, __shfl_xor_sync(0xffffffffu, tm0, 1));
        tm0 = fmaxf(tm0, __shfl_xor_sync(0xffffffffu, tm0, 2));
        tm1 = fmaxf(tm1, __shfl_xor_sync(0xffffffffu, tm1, 1));
        tm1 = fmaxf(tm1, __shfl_xor_sync(0xffffffffu, tm1, 2));
        float m0 = fmaxf(mrow0, tm0), m1 = fmaxf(mrow1, tm1);
        float a0 = __expf(mrow0 - m0), a1 = __expf(mrow1 - m1);
        mrow0 = m0; mrow1 = m1;
        float rs0 = 0.f, rs1 = 0.f;
#pragma unroll
        for (int nt = 0; nt < 8; nt++) {
            sacc[nt][0] = __expf(sacc[nt][0] - m0); rs0 += sacc[nt][0];
            sacc[nt][1] = __expf(sacc[nt][1] - m0); rs0 += sacc[nt][1];
            sacc[nt][2] = __expf(sacc[nt][2] - m1); rs1 += sacc[nt][2];
            sacc[nt][3] = __expf(sacc[nt][3] - m1); rs1 += sacc[nt][3];
        }
        rs0 += __shfl_xor_sync(0xffffffffu, rs0, 1);
        rs0 += __shfl_xor_sync(0xffffffffu, rs0, 2);
        rs1 += __shfl_xor_sync(0xffffffffu, rs1, 1);
        rs1 += __shfl_xor_sync(0xffffffffu, rs1, 2);
        lrow0 = lrow0 * a0 + rs0;
        lrow1 = lrow1 * a1 + rs1;
#pragma unroll
        for (int nt = 0; nt < 8; nt++) {
            oacc[nt][0] *= a0; oacc[nt][1] *= a0;
            oacc[nt][2] *= a1; oacc[nt][3] *= a1;
        }

        // O += P @ V — P from sacc registers ([c0,c2,c1,c3], pos_v V tokens)
#pragma unroll
        for (int kk = 0; kk < 8; kk++) {
            const uint32_t kx = (((uint32_t)(kk * 8) + ko) ^ sw4) << 2;
            uint32_t af[4], bf[8][2], bt4[4];
            af[0] = __float_as_uint(rn_tf32(sacc[kk][0]));
            af[1] = __float_as_uint(rn_tf32(sacc[kk][2]));
            af[2] = __float_as_uint(rn_tf32(sacc[kk][1]));
            af[3] = __float_as_uint(rn_tf32(sacc[kk][3]));
#pragma unroll
            for (int p = 0; p < 4; p++) {
                ldsm_x4(bt4, vsb + n_rb[p] + kx);
                bf[2 * p][0]     = bt4[0];
                bf[2 * p + 1][0] = bt4[1];
                bf[2 * p][1]     = bt4[2];
                bf[2 * p + 1][1] = bt4[3];
            }
#pragma unroll
            for (int nt = 0; nt < 8; nt++)
                mma_tf32(oacc[nt], af, bf[nt]);
        }
    }

    // normalize + store, col-permuted (feeds proj GEMM's permuted A)
    float inv0 = 1.0f / lrow0, inv1 = 1.0f / lrow1;
    float* ybase = y + ((size_t)(b * TT + q0)) * CC + h * HD;
#pragma unroll
    for (int nt = 0; nt < 8; nt++) {
        int cb = nt * 8;
        ybase[(size_t)r0 * CC + cb + pp0]       = rn_tf32(oacc[nt][0] * inv0);
        ybase[(size_t)r0 * CC + cb + pp1]       = rn_tf32(oacc[nt][1] * inv0);
        ybase[(size_t)(r0 + 8) * CC + cb + pp0] = rn_tf32(oacc[nt][2] * inv1);
        ybase[(size_t)(r0 + 8) * CC + cb + pp1] = rn_tf32(oacc[nt][3] * inv1);
    }
}

// ---------------------------------------------------------------- launch
extern "C" void kernel_launch(void* const* d_in, const int* in_sizes, int n_in,
                              void* d_out, int out_size)
{
    const float* x      = (const float*)d_in[0];
    const float* w_attn = (const float*)d_in[1];
    const float* b_attn = (const float*)d_in[2];
    const float* w_proj = (const float*)d_in[3];
    const float* b_proj = (const float*)d_in[4];
    float* out = (float*)d_out;

    float *qkv, *vt, *yb, *xp, *waT, *wpT;
    cudaGetSymbolAddress((void**)&qkv, g_qkv);
    cudaGetSymbolAddress((void**)&vt,  g_vt);
    cudaGetSymbolAddress((void**)&yb,  g_y);
    cudaGetSymbolAddress((void**)&xp,  g_xp);
    cudaGetSymbolAddress((void**)&waT, g_waT);
    cudaGetSymbolAddress((void**)&wpT, g_wpT);

    cudaFuncSetAttribute(gemm_tf32, cudaFuncAttributeMaxDynamicSharedMemorySize, GEMM_SMEM);
    cudaFuncSetAttribute(attn_tc,   cudaFuncAttributeMaxDynamicSharedMemorySize, ATTN_SMEM);

    round_perm_kernel<<<(BT * CC) / (256 * 8), 256>>>(x, xp);
    transpose_perm_kernel<<<dim3(C3 / 32, CC / 32), dim3(32, 8)>>>(w_attn, waT, CC, C3);
    transpose_perm_kernel<<<dim3(CC / 32, CC / 32), dim3(32, 8)>>>(w_proj, wpT, CC, CC);

    gemm_tf32<<<dim3(C3 / GBN, BT / GBM), 256, GEMM_SMEM>>>(xp, waT, b_attn, qkv, vt,
                                                            BT, C3, CC, 1);

    attn_tc<<<dim3(TT / AQ, NH, BB), 128, ATTN_SMEM>>>(qkv, vt, yb);

    gemm_tf32<<<dim3(CC / GBN, BT / GBM), 256, GEMM_SMEM>>>(yb, wpT, b_proj, out, vt,
                                                            BT, CC, CC, 0);
}

// round 14
// speedup vs baseline: 1.2571x; 1.0842x over previous
#include <cuda_runtime.h>
#include <cstdint>
#include <cmath>

// ---------------------------------------------------------------- constants
#define BB   2
#define TT   2048
#define CC   1024
#define NH   16
#define HD   64
#define BT   (BB*TT)          // 4096
#define C3   (3*CC)           // 3072
#define SCALE 0.125f

// ---------------------------------------------------------------- scratch
__device__ float g_qkv[(size_t)BT * C3];        // Q,K regions (cols<2048), col-permuted
__device__ float g_vt [(size_t)BB*NH*HD*TT];    // V transposed [b,h,d,token], pos_v tokens
__device__ float g_y  [(size_t)BT * CC];        // attention out, PACKED tiles (proj A)
__device__ float g_xp [(size_t)BT * CC];        // x, PACKED tiles (QKV A)
__device__ float g_waT[(size_t)C3 * CC];        // w_attn, PACKED tiles over [N,K]
__device__ float g_wpT[(size_t)CC * CC];        // w_proj, PACKED tiles over [N,K]

// Packed operand layout: tiles of 128 rows x 32 k (16KB), tile-contiguous,
// pre-swizzled exactly like GEMM smem: off = r*32 + ((kc&~3) ^ 4*(r&7)) + (kc&3),
// k-dim already 8-group permuted ([0,4,1,5,2,6,3,7] gather).

// ---------------------------------------------------------------- utils
__device__ __forceinline__ uint32_t smem_u32(const void* p) {
    uint32_t a;
    asm("{ .reg .u64 t; cvta.to.shared.u64 t, %1; cvt.u32.u64 %0, t; }" : "=r"(a) : "l"(p));
    return a;
}
__device__ __forceinline__ float rn_tf32(float x) {
    uint32_t r;
    asm("cvt.rna.tf32.f32 %0, %1;" : "=r"(r) : "f"(x));
    return __uint_as_float(r);
}
#define CP_ASYNC16(dst, src) \
    asm volatile("cp.async.cg.shared.global [%0], [%1], 16;\n" :: "r"(dst), "l"(src))
#define CP_COMMIT() asm volatile("cp.async.commit_group;" ::: "memory")
#define CP_WAIT(n)  asm volatile("cp.async.wait_group %0;" :: "n"(n) : "memory")

#define MBAR_INIT(m, c) \
    asm volatile("mbarrier.init.shared.b64 [%0], %1;" :: "r"(m), "r"((uint32_t)(c)) : "memory")
#define MBAR_EXPECT(m, bytes) \
    asm volatile("mbarrier.arrive.expect_tx.shared.b64 _, [%0], %1;" \
                 :: "r"(m), "r"((uint32_t)(bytes)) : "memory")
#define CP_BULK(dst, src, bytes, mbar) \
    asm volatile("cp.async.bulk.shared::cluster.global.mbarrier::complete_tx::bytes " \
                 "[%0], [%1], %2, [%3];" \
                 :: "r"(dst), "l"(src), "r"((uint32_t)(bytes)), "r"(mbar) : "memory")
#define MBAR_WAIT(mbar, parity) do { \
    uint32_t _m = (uint32_t)(mbar); uint32_t _p = (uint32_t)(parity); uint32_t _done; \
    asm volatile("{\n\t.reg .pred p;\n\t" \
        "mbarrier.try_wait.parity.acquire.cta.shared::cta.b64 p, [%1], %2;\n\t" \
        "selp.b32 %0, 1, 0, p;\n\t}" : "=r"(_done) : "r"(_m), "r"(_p) : "memory"); \
    if (!_done) { \
        asm volatile("{\n\t.reg .pred P1;\n\t" \
            "WL_%=:\n\t" \
            "mbarrier.try_wait.parity.acquire.cta.shared::cta.b64 P1, [%0], %1, 0x989680;\n\t" \
            "@P1 bra.uni WD_%=;\n\t" \
            "bra.uni WL_%=;\n\t" \
            "WD_%=:\n\t}" :: "r"(_m), "r"(_p) : "memory"); \
    } } while (0)

__device__ __forceinline__ void mma_tf32(float* c, const uint32_t* a, const uint32_t* b) {
    asm volatile(
        "mma.sync.aligned.m16n8k8.row.col.f32.tf32.tf32.f32 "
        "{%0,%1,%2,%3}, {%4,%5,%6,%7}, {%8,%9}, {%0,%1,%2,%3};"
        : "+f"(c[0]), "+f"(c[1]), "+f"(c[2]), "+f"(c[3])
        : "r"(a[0]), "r"(a[1]), "r"(a[2]), "r"(a[3]), "r"(b[0]), "r"(b[1]));
}
__device__ __forceinline__ void ldsm_x4(uint32_t* r, uint32_t addr) {
    asm volatile("ldmatrix.sync.aligned.m8n8.x4.shared.b16 {%0,%1,%2,%3}, [%4];"
        : "=r"(r[0]), "=r"(r[1]), "=r"(r[2]), "=r"(r[3]) : "r"(addr));
}
// position of natural u in its 8-group under gather [0,4,1,5,2,6,3,7]
__device__ __forceinline__ int perm8(int u) { return u < 4 ? 2 * u : 2 * u - 7; }
// natural source index for permuted position p (inverse): g(p)
__device__ __forceinline__ int gath8(int p) { return ((p & 7) >> 1) + (p & 1) * 4 + (p & ~7); }
// V-token permutation: position of natural u under gather_v [0,2,4,6,1,3,5,7]
__device__ __forceinline__ int posv(int u) { return (u >> 1) + (u & 1) * 4; }
// packed-operand element address (row-major rows, K columns; tilesPerRow = K/32)
__device__ __forceinline__ size_t packaddr(int row, int col, int tpr) {
    int tile = (row >> 7) * tpr + (col >> 5);
    int r = row & 127, kc = col & 31;
    return (size_t)tile * 4096 + r * 32 + (((kc & ~3) ^ (4 * (r & 7))) | (kc & 3));
}

// ---------------------------------------------------------------- prep
// x [M,K] fp32 -> packed tiles (rn_tf32 + k-perm folded). One thread per 16B beat.
__global__ void pack_a_kernel(const float* __restrict__ in, float* __restrict__ out, int K) {
    size_t u = (size_t)blockIdx.x * blockDim.x + threadIdx.x;
    int c4 = (int)(u & 7);              // k-beat in tile row
    int r  = (int)((u >> 3) & 127);     // row in tile
    size_t tile = u >> 10;              // 1024 beats per tile
    int mt = (int)(tile / (K / 32)), kb = (int)(tile % (K / 32));
    const float* src = in + (size_t)(mt * 128 + r) * K + kb * 32;
    int p0 = c4 * 4;
    float4 v;
    v.x = rn_tf32(src[gath8(p0 + 0)]);
    v.y = rn_tf32(src[gath8(p0 + 1)]);
    v.z = rn_tf32(src[gath8(p0 + 2)]);
    v.w = rn_tf32(src[gath8(p0 + 3)]);
    *(float4*)(out + tile * 4096 + r * 32 + (p0 ^ (4 * (r & 7)))) = v;
}

// w [K,N] -> packed tiles over [N,K] (transpose + rn + k-perm folded)
__global__ void transpose_pack_kernel(const float* __restrict__ in, float* __restrict__ out,
                                      int K, int N) {
    __shared__ float tsm[32][33];
    int k0 = blockIdx.y * 32, n0 = blockIdx.x * 32;
    int tx = threadIdx.x, ty = threadIdx.y;     // 32 x 8
#pragma unroll
    for (int i = 0; i < 32; i += 8)
        tsm[ty + i][tx] = in[(size_t)(k0 + ty + i) * N + n0 + tx];
    __syncthreads();
    int kk = gath8(tx);                         // natural k for permuted position tx
    int tpr = K / 32;
#pragma unroll
    for (int i = 0; i < 32; i += 8) {
        int nr = n0 + ty + i;
        out[packaddr(nr, k0 + tx, tpr)] = rn_tf32(tsm[kk][ty + i]);
    }
}

// ---------------------------------------------------------------- tf32 GEMM
// A, Bt are PACKED operands. Stage load = 2 cp.async.bulk (16KB each), mbarrier sync.
#define GBM 128
#define GBN 128
#define GBK 32
#define GSTG 3
#define TILE_B 16384                          // bytes per operand tile
#define SM_B_OFF (GSTG * TILE_B)              // B stages after A stages (49152)
#define SM_MBAR  (2 * GSTG * TILE_B)          // 98304
#define GEMM_SMEM (SM_MBAR + 64)

__global__ __launch_bounds__(256, 2) void gemm_tf32(
    const float* __restrict__ A, const float* __restrict__ Bt,
    const float* __restrict__ bias, float* __restrict__ C,
    float* __restrict__ vt, int M, int N, int K, int mode)
{
    extern __shared__ float smf[];
    const uint32_t smb = smem_u32(smf);
    const uint32_t mb = smb + SM_MBAR;

    const int tid = threadIdx.x, wid = tid >> 5, lane = tid & 31;
    const int g = lane >> 2, t = lane & 3;
    const int wm = wid & 3, wn = wid >> 2;
    const int m0 = blockIdx.y * GBM, n0 = blockIdx.x * GBN;
    const int NCH = K / GBK;

    if (tid == 0) {
        MBAR_INIT(mb + 0, 1); MBAR_INIT(mb + 8, 1); MBAR_INIT(mb + 16, 1);
    }
    __syncthreads();

    const float* a_src = A  + ((size_t)(m0 >> 7) * NCH) * 4096;
    const float* b_src = Bt + ((size_t)(n0 >> 7) * NCH) * 4096;

    if (tid == 0) {
#pragma unroll
        for (int s = 0; s < GSTG - 1; s++) {
            MBAR_EXPECT(mb + 8 * s, 2 * TILE_B);
            CP_BULK(smb + s * TILE_B,            a_src + s * 4096, TILE_B, mb + 8 * s);
            CP_BULK(smb + SM_B_OFF + s * TILE_B, b_src + s * 4096, TILE_B, mb + 8 * s);
        }
    }

    // ldmatrix per-lane geometry
    const int lq = lane >> 3, li = lane & 7;
    const uint32_t sw4 = 4u * (uint32_t)li;
    const uint32_t ko  = (uint32_t)((lq >> 1) * 4);
    uint32_t a_rb[2], b_rb[4];
#pragma unroll
    for (int mt = 0; mt < 2; mt++)
        a_rb[mt] = (uint32_t)(wm * 32 + mt * 16 + (lq & 1) * 8 + li) * 128u;
#pragma unroll
    for (int p = 0; p < 4; p++)
        b_rb[p] = (uint32_t)(wn * 64 + p * 16 + (lq & 1) * 8 + li) * 128u;

    float acc[2][8][4];
#pragma unroll
    for (int mt = 0; mt < 2; mt++)
#pragma unroll
        for (int nt = 0; nt < 8; nt++)
#pragma unroll
            for (int k = 0; k < 4; k++) acc[mt][nt][k] = 0.f;

    int s_use = 0, ph = 0, s_fill = GSTG - 1;
    for (int kb = 0; kb < NCH; kb++) {
        MBAR_WAIT(mb + 8 * s_use, ph);
        __syncthreads();

        if (kb + GSTG - 1 < NCH && tid == 0) {
            MBAR_EXPECT(mb + 8 * s_fill, 2 * TILE_B);
            CP_BULK(smb + s_fill * TILE_B,            a_src + (kb + GSTG - 1) * 4096,
                    TILE_B, mb + 8 * s_fill);
            CP_BULK(smb + SM_B_OFF + s_fill * TILE_B, b_src + (kb + GSTG - 1) * 4096,
                    TILE_B, mb + 8 * s_fill);
        }

        const uint32_t asb = smb + s_use * TILE_B;
        const uint32_t bsb = smb + SM_B_OFF + s_use * TILE_B;
#pragma unroll
        for (int ks = 0; ks < 4; ks++) {
            const uint32_t kx = (((uint32_t)(ks * 8) + ko) ^ sw4) * 4u;
            uint32_t af[2][4], bf[8][2], bt4[4];
            ldsm_x4(af[0], asb + a_rb[0] + kx);
            ldsm_x4(af[1], asb + a_rb[1] + kx);
#pragma unroll
            for (int p = 0; p < 4; p++) {
                ldsm_x4(bt4, bsb + b_rb[p] + kx);
                bf[2 * p][0]     = bt4[0];
                bf[2 * p + 1][0] = bt4[1];
                bf[2 * p][1]     = bt4[2];
                bf[2 * p + 1][1] = bt4[3];
            }
#pragma unroll
            for (int mt = 0; mt < 2; mt++)
#pragma unroll
                for (int nt = 0; nt < 8; nt++)
                    mma_tf32(acc[mt][nt], af[mt], bf[nt]);
        }
        if (++s_fill == GSTG) s_fill = 0;
        if (++s_use == GSTG) { s_use = 0; ph ^= 1; }
    }

    // epilogue
#pragma unroll
    for (int mt = 0; mt < 2; mt++) {
        int r0 = m0 + wm * 32 + mt * 16 + g;
#pragma unroll
        for (int nt = 0; nt < 8; nt++) {
            int c = n0 + wn * 64 + nt * 8 + 2 * t;
            float2 b2 = *(const float2*)(bias + c);
            float2 v0 = make_float2(acc[mt][nt][0] + b2.x, acc[mt][nt][1] + b2.y);
            float2 v1 = make_float2(acc[mt][nt][2] + b2.x, acc[mt][nt][3] + b2.y);
            if (mode == 1) {
                v0.x = rn_tf32(v0.x); v0.y = rn_tf32(v0.y);
                v1.x = rn_tf32(v1.x); v1.y = rn_tf32(v1.y);
                if (c < 2048) {
                    int c0p = (c & ~7) | perm8(c & 7);
                    int c1p = (c & ~7) | perm8((c & 7) + 1);
                    C[(size_t)r0 * N + c0p] = v0.x;
                    C[(size_t)r0 * N + c1p] = v0.y;
                    C[(size_t)(r0 + 8) * N + c0p] = v1.x;
                    C[(size_t)(r0 + 8) * N + c1p] = v1.y;
                } else {
                    int h  = (c - 2048) >> 6;
                    int d0 = (c - 2048) & 63;
                    int b0  = r0 >> 11;
                    int tp0 = ((r0 & 2047) & ~7) | posv(r0 & 7);
                    int tp1 = (((r0 + 8) & 2047) & ~7) | posv((r0 + 8) & 7);
                    float* vb = vt + ((size_t)(b0 * NH + h) * HD + d0) * TT;
                    vb[tp0]      = v0.x;
                    vb[TT + tp0] = v0.y;
                    vb[tp1]      = v1.x;
                    vb[TT + tp1] = v1.y;
                }
            } else {
                *(float2*)(C + (size_t)r0 * N + c) = v0;
                *(float2*)(C + (size_t)(r0 + 8) * N + c) = v1;
            }
        }
    }
}

// ---------------------------------------------------------------- attention (R11, y packed out)
#define AQ 64
#define AK 64
#define SM_QS 0
#define SM_KS 4096
#define SM_VS (SM_KS + 2*4096)
#define ATTN_SMEM ((SM_VS + 2*4096) * 4)     // 81920 B

__global__ __launch_bounds__(128, 2) void attn_tc(const float* __restrict__ qkv,
                                                  const float* __restrict__ vt,
                                                  float* __restrict__ y)
{
    extern __shared__ float sm[];
    const int tid = threadIdx.x;
    const int wid = tid >> 5, lane = tid & 31;
    const int g = lane >> 2, t = lane & 3;
    const int qt = gridDim.x - 1 - blockIdx.x;
    const int h  = blockIdx.y;
    const int b  = blockIdx.z;
    const int q0 = qt * AQ;
    const int r0 = wid * 16 + g;
    const uint32_t smb = smem_u32(sm);

    const int lq = lane >> 3, li = lane & 7;
    const uint32_t sw4 = 4u * (uint32_t)li;
    const uint32_t ko  = (uint32_t)((lq >> 1) * 4);
    const uint32_t rq  = (uint32_t)((lq & 1) * 8 + li);
    const uint32_t q_rb = (uint32_t)(wid * 16 + rq) * 256u;
    uint32_t n_rb[4];
#pragma unroll
    for (int p = 0; p < 4; p++) n_rb[p] = (uint32_t)(p * 16 + rq) * 256u;

    uint32_t st_off[8], kg[8], vg[8];
#pragma unroll
    for (int i = 0; i < 8; i++) {
        int idx = tid + i * 128, row = idx >> 4, c4 = idx & 15;
        st_off[i] = (uint32_t)(row * 64 + ((c4 * 4) ^ (4 * (row & 7)))) * 4u;
        kg[i] = (uint32_t)(row * C3 + c4 * 4);
        vg[i] = (uint32_t)(row * TT + c4 * 4);
    }
    const float* kb0 = qkv + ((size_t)(b * TT)) * C3 + CC + h * HD;
    const float* vb0 = vt + ((size_t)(b * NH + h) * HD) * TT;

    {
        const float* qbase = qkv + ((size_t)(b * TT + q0)) * C3 + h * HD;
#pragma unroll
        for (int i = 0; i < 8; i++) {
            int idx = tid + i * 128, row = idx >> 4, c4 = idx & 15;
            float4 v = *(const float4*)(qbase + (size_t)row * C3 + c4 * 4);
            v.x *= SCALE; v.y *= SCALE; v.z *= SCALE; v.w *= SCALE;
            *(float4*)(&sm[SM_QS + row * 64 + ((c4 * 4) ^ (4 * (row & 7)))]) = v;
        }
    }
    {
        uint32_t kd = smb + SM_KS * 4, vd = smb + SM_VS * 4;
#pragma unroll
        for (int i = 0; i < 8; i++) {
            CP_ASYNC16(kd + st_off[i], kb0 + kg[i]);
            CP_ASYNC16(vd + st_off[i], vb0 + vg[i]);
        }
    }
    CP_COMMIT();
    __syncthreads();

    uint32_t qf[8][4];
#pragma unroll
    for (int ds = 0; ds < 8; ds++)
        ldsm_x4(qf[ds], smb + SM_QS * 4 + q_rb + ((((uint32_t)(ds * 8) + ko) ^ sw4) << 2));

    float oacc[8][4];
#pragma unroll
    for (int nt = 0; nt < 8; nt++)
#pragma unroll
        for (int k = 0; k < 4; k++) oacc[nt][k] = 0.f;
    float mrow0 = -INFINITY, mrow1 = -INFINITY, lrow0 = 0.f, lrow1 = 0.f;

    const int pp0 = perm8(2 * t), pp1 = perm8(2 * t + 1);

    for (int kt = 0; kt <= qt; kt++) {
        const int buf = kt & 1;
        CP_WAIT(0);
        __syncthreads();
        if (kt < qt) {
            uint32_t kd = smb + (SM_KS + (buf ^ 1) * 4096) * 4;
            uint32_t vd = smb + (SM_VS + (buf ^ 1) * 4096) * 4;
            const float* kp = kb0 + (size_t)(kt + 1) * 64 * C3;
            const float* vp = vb0 + (kt + 1) * 64;
#pragma unroll
            for (int i = 0; i < 8; i++) {
                CP_ASYNC16(kd + st_off[i], kp + kg[i]);
                CP_ASYNC16(vd + st_off[i], vp + vg[i]);
            }
        }
        CP_COMMIT();

        const uint32_t ksb = smb + (SM_KS + buf * 4096) * 4;
        const uint32_t vsb = smb + (SM_VS + buf * 4096) * 4;

        float sacc[8][4];
#pragma unroll
        for (int nt = 0; nt < 8; nt++)
#pragma unroll
            for (int k = 0; k < 4; k++) sacc[nt][k] = 0.f;
#pragma unroll
        for (int ds = 0; ds < 8; ds++) {
            const uint32_t kx = (((uint32_t)(ds * 8) + ko) ^ sw4) << 2;
            uint32_t bf[8][2], bt4[4];
#pragma unroll
            for (int p = 0; p < 4; p++) {
                ldsm_x4(bt4, ksb + n_rb[p] + kx);
                bf[2 * p][0]     = bt4[0];
                bf[2 * p + 1][0] = bt4[1];
                bf[2 * p][1]     = bt4[2];
                bf[2 * p + 1][1] = bt4[3];
            }
#pragma unroll
            for (int nt = 0; nt < 8; nt++)
                mma_tf32(sacc[nt], qf[ds], bf[nt]);
        }

        if (kt == qt) {
#pragma unroll
            for (int nt = 0; nt < 8; nt++) {
                int c = nt * 8 + 2 * t;
                if (c     > r0)     sacc[nt][0] = -1e30f;
                if (c + 1 > r0)     sacc[nt][1] = -1e30f;
                if (c     > r0 + 8) sacc[nt][2] = -1e30f;
                if (c + 1 > r0 + 8) sacc[nt][3] = -1e30f;
            }
        }

        float tm0 = -INFINITY, tm1 = -INFINITY;
#pragma unroll
        for (int nt = 0; nt < 8; nt++) {
            tm0 = fmaxf(tm0, fmaxf(sacc[nt][0], sacc[nt][1]));
            tm1 = fmaxf(tm1, fmaxf(sacc[nt][2], sacc[nt][3]));
        }
        tm0 = fmaxf(tm0, __shfl_xor_sync(0xffffffffu, tm0, 1));
        tm0 = fmaxf(tm0, __shfl_xor_sync(0xffffffffu, tm0, 2));
        tm1 = fmaxf(tm1, __shfl_xor_sync(0xffffffffu, tm1, 1));
        tm1 = fmaxf(tm1, __shfl_xor_sync(0xffffffffu, tm1, 2));
        float m0 = fmaxf(mrow0, tm0), m1 = fmaxf(mrow1, tm1);
        float a0 = __expf(mrow0 - m0), a1 = __expf(mrow1 - m1);
        mrow0 = m0; mrow1 = m1;
        float rs0 = 0.f, rs1 = 0.f;
#pragma unroll
        for (int nt = 0; nt < 8; nt++) {
            sacc[nt][0] = __expf(sacc[nt][0] - m0); rs0 += sacc[nt][0];
            sacc[nt][1] = __expf(sacc[nt][1] - m0); rs0 += sacc[nt][1];
            sacc[nt][2] = __expf(sacc[nt][2] - m1); rs1 += sacc[nt][2];
            sacc[nt][3] = __expf(sacc[nt][3] - m1); rs1 += sacc[nt][3];
        }
        rs0 += __shfl_xor_sync(0xffffffffu, rs0, 1);
        rs0 += __shfl_xor_sync(0xffffffffu, rs0, 2);
        rs1 += __shfl_xor_sync(0xffffffffu, rs1, 1);
        rs1 += __shfl_xor_sync(0xffffffffu, rs1, 2);
        lrow0 = lrow0 * a0 + rs0;
        lrow1 = lrow1 * a1 + rs1;
#pragma unroll
        for (int nt = 0; nt < 8; nt++) {
            oacc[nt][0] *= a0; oacc[nt][1] *= a0;
            oacc[nt][2] *= a1; oacc[nt][3] *= a1;
        }

#pragma unroll
        for (int kk = 0; kk < 8; kk++) {
            const uint32_t kx = (((uint32_t)(kk * 8) + ko) ^ sw4) << 2;
            uint32_t af[4], bf[8][2], bt4[4];
            af[0] = __float_as_uint(rn_tf32(sacc[kk][0]));
            af[1] = __float_as_uint(rn_tf32(sacc[kk][2]));
            af[2] = __float_as_uint(rn_tf32(sacc[kk][1]));
            af[3] = __float_as_uint(rn_tf32(sacc[kk][3]));
#pragma unroll
            for (int p = 0; p < 4; p++) {
                ldsm_x4(bt4, vsb + n_rb[p] + kx);
                bf[2 * p][0]     = bt4[0];
                bf[2 * p + 1][0] = bt4[1];
                bf[2 * p][1]     = bt4[2];
                bf[2 * p + 1][1] = bt4[3];
            }
#pragma unroll
            for (int nt = 0; nt < 8; nt++)
                mma_tf32(oacc[nt], af, bf[nt]);
        }
    }

    // normalize + store into PACKED y (proj GEMM's A), perm folded into col
    float inv0 = 1.0f / lrow0, inv1 = 1.0f / lrow1;
    const int row0 = b * TT + q0 + r0;
    const int row1 = row0 + 8;
#pragma unroll
    for (int nt = 0; nt < 8; nt++) {
        int c0 = h * HD + nt * 8 + pp0;
        int c1 = h * HD + nt * 8 + pp1;
        y[packaddr(row0, c0, 32)] = rn_tf32(oacc[nt][0] * inv0);
        y[packaddr(row0, c1, 32)] = rn_tf32(oacc[nt][1] * inv0);
        y[packaddr(row1, c0, 32)] = rn_tf32(oacc[nt][2] * inv1);
        y[packaddr(row1, c1, 32)] = rn_tf32(oacc[nt][3] * inv1);
    }
}

// ---------------------------------------------------------------- launch
extern "C" void kernel_launch(void* const* d_in, const int* in_sizes, int n_in,
                              void* d_out, int out_size)
{
    const float* x      = (const float*)d_in[0];
    const float* w_attn = (const float*)d_in[1];
    const float* b_attn = (const float*)d_in[2];
    const float* w_proj = (const float*)d_in[3];
    const float* b_proj = (const float*)d_in[4];
    float* out = (float*)d_out;

    float *qkv, *vt, *yb, *xp, *waT, *wpT;
    cudaGetSymbolAddress((void**)&qkv, g_qkv);
    cudaGetSymbolAddress((void**)&vt,  g_vt);
    cudaGetSymbolAddress((void**)&yb,  g_y);
    cudaGetSymbolAddress((void**)&xp,  g_xp);
    cudaGetSymbolAddress((void**)&waT, g_waT);
    cudaGetSymbolAddress((void**)&wpT, g_wpT);

    cudaFuncSetAttribute(gemm_tf32, cudaFuncAttributeMaxDynamicSharedMemorySize, GEMM_SMEM);
    cudaFuncSetAttribute(attn_tc,   cudaFuncAttributeMaxDynamicSharedMemorySize, ATTN_SMEM);

    // 0) pack operands (rn_tf32 + perm + swizzle folded into packed tiles)
    pack_a_kernel<<<(BT * CC / 4) / 256, 256>>>(x, xp, CC);
    transpose_pack_kernel<<<dim3(C3 / 32, CC / 32), dim3(32, 8)>>>(w_attn, waT, CC, C3);
    transpose_pack_kernel<<<dim3(CC / 32, CC / 32), dim3(32, 8)>>>(w_proj, wpT, CC, CC);

    // 1) QKV GEMM (bulk-staged packed operands; Q/K -> qkv permuted, V -> vt)
    gemm_tf32<<<dim3(C3 / GBN, BT / GBM), 256, GEMM_SMEM>>>(xp, waT, b_attn, qkv, vt,
                                                            BT, C3, CC, 1);

    // 2) causal attention (R11 structure; writes packed y)
    attn_tc<<<dim3(TT / AQ, NH, BB), 128, ATTN_SMEM>>>(qkv, vt, yb);

    // 3) out = y @ w_proj + b_proj (bulk-staged packed operands; natural output)
    gemm_tf32<<<dim3(CC / GBN, BT / GBM), 256, GEMM_SMEM>>>(yb, wpT, b_proj, out, vt,
                                                            BT, CC, CC, 0);
}

// round 15
// speedup vs baseline: 1.2962x; 1.0311x over previous
#include <cuda_runtime.h>
#include <cstdint>
#include <cmath>

// ---------------------------------------------------------------- constants
#define BB   2
#define TT   2048
#define CC   1024
#define NH   16
#define HD   64
#define BT   (BB*TT)          // 4096
#define C3   (3*CC)           // 3072
#define SCALE 0.125f

// ---------------------------------------------------------------- scratch
__device__ float g_qkv[(size_t)BT * C3];        // Q region (cols<1024), col-permuted
__device__ float g_kp [(size_t)BB*NH*32*4096]; // K packed tiles [b,h,kt][tok][d-perm], swizzled
__device__ float g_vp [(size_t)BB*NH*32*4096]; // V packed tiles [b,h,kt][d][tok-posv], swizzled
__device__ float g_y  [(size_t)BT * CC];        // attention out, PACKED tiles (proj A)
__device__ float g_xp [(size_t)BT * CC];        // x, PACKED tiles (QKV A)
__device__ float g_waT[(size_t)C3 * CC];        // w_attn, PACKED tiles over [N,K]
__device__ float g_wpT[(size_t)CC * CC];        // w_proj, PACKED tiles over [N,K]

// ---------------------------------------------------------------- utils
__device__ __forceinline__ uint32_t smem_u32(const void* p) {
    uint32_t a;
    asm("{ .reg .u64 t; cvta.to.shared.u64 t, %1; cvt.u32.u64 %0, t; }" : "=r"(a) : "l"(p));
    return a;
}
__device__ __forceinline__ float rn_tf32(float x) {
    uint32_t r;
    asm("cvt.rna.tf32.f32 %0, %1;" : "=r"(r) : "f"(x));
    return __uint_as_float(r);
}
#define CP_COMMIT() asm volatile("cp.async.commit_group;" ::: "memory")

#define MBAR_INIT(m, c) \
    asm volatile("mbarrier.init.shared.b64 [%0], %1;" :: "r"(m), "r"((uint32_t)(c)) : "memory")
#define MBAR_EXPECT(m, bytes) \
    asm volatile("mbarrier.arrive.expect_tx.shared.b64 _, [%0], %1;" \
                 :: "r"(m), "r"((uint32_t)(bytes)) : "memory")
#define CP_BULK(dst, src, bytes, mbar) \
    asm volatile("cp.async.bulk.shared::cluster.global.mbarrier::complete_tx::bytes " \
                 "[%0], [%1], %2, [%3];" \
                 :: "r"(dst), "l"(src), "r"((uint32_t)(bytes)), "r"(mbar) : "memory")
#define MBAR_WAIT(mbar, parity) do { \
    uint32_t _m = (uint32_t)(mbar); uint32_t _p = (uint32_t)(parity); uint32_t _done; \
    asm volatile("{\n\t.reg .pred p;\n\t" \
        "mbarrier.try_wait.parity.acquire.cta.shared::cta.b64 p, [%1], %2;\n\t" \
        "selp.b32 %0, 1, 0, p;\n\t}" : "=r"(_done) : "r"(_m), "r"(_p) : "memory"); \
    if (!_done) { \
        asm volatile("{\n\t.reg .pred P1;\n\t" \
            "WL_%=:\n\t" \
            "mbarrier.try_wait.parity.acquire.cta.shared::cta.b64 P1, [%0], %1, 0x989680;\n\t" \
            "@P1 bra.uni WD_%=;\n\t" \
            "bra.uni WL_%=;\n\t" \
            "WD_%=:\n\t}" :: "r"(_m), "r"(_p) : "memory"); \
    } } while (0)

__device__ __forceinline__ void mma_tf32(float* c, const uint32_t* a, const uint32_t* b) {
    asm volatile(
        "mma.sync.aligned.m16n8k8.row.col.f32.tf32.tf32.f32 "
        "{%0,%1,%2,%3}, {%4,%5,%6,%7}, {%8,%9}, {%0,%1,%2,%3};"
        : "+f"(c[0]), "+f"(c[1]), "+f"(c[2]), "+f"(c[3])
        : "r"(a[0]), "r"(a[1]), "r"(a[2]), "r"(a[3]), "r"(b[0]), "r"(b[1]));
}
__device__ __forceinline__ void ldsm_x4(uint32_t* r, uint32_t addr) {
    asm volatile("ldmatrix.sync.aligned.m8n8.x4.shared.b16 {%0,%1,%2,%3}, [%4];"
        : "=r"(r[0]), "=r"(r[1]), "=r"(r[2]), "=r"(r[3]) : "r"(addr));
}
// position of natural u in its 8-group under gather [0,4,1,5,2,6,3,7]
__device__ __forceinline__ int perm8(int u) { return u < 4 ? 2 * u : 2 * u - 7; }
// natural source index for permuted position p
__device__ __forceinline__ int gath8(int p) { return ((p & 7) >> 1) + (p & 1) * 4 + (p & ~7); }
// V-token permutation: position of natural u under gather_v [0,2,4,6,1,3,5,7]
__device__ __forceinline__ int posv(int u) { return (u >> 1) + (u & 1) * 4; }
// swizzled offset within a 64-col tile row
__device__ __forceinline__ int swz64(int r, int c) {
    return r * 64 + (((c & ~3) ^ (4 * (r & 7))) | (c & 3));
}
// packed GEMM-operand element address (128x32 tiles)
__device__ __forceinline__ size_t packaddr(int row, int col, int tpr) {
    int tile = (row >> 7) * tpr + (col >> 5);
    int r = row & 127, kc = col & 31;
    return (size_t)tile * 4096 + r * 32 + (((kc & ~3) ^ (4 * (r & 7))) | (kc & 3));
}

// ---------------------------------------------------------------- prep
__global__ void pack_a_kernel(const float* __restrict__ in, float* __restrict__ out, int K) {
    size_t u = (size_t)blockIdx.x * blockDim.x + threadIdx.x;
    int c4 = (int)(u & 7);
    int r  = (int)((u >> 3) & 127);
    size_t tile = u >> 10;
    int mt = (int)(tile / (K / 32)), kb = (int)(tile % (K / 32));
    const float* src = in + (size_t)(mt * 128 + r) * K + kb * 32;
    int p0 = c4 * 4;
    float4 v;
    v.x = rn_tf32(src[gath8(p0 + 0)]);
    v.y = rn_tf32(src[gath8(p0 + 1)]);
    v.z = rn_tf32(src[gath8(p0 + 2)]);
    v.w = rn_tf32(src[gath8(p0 + 3)]);
    *(float4*)(out + tile * 4096 + r * 32 + (p0 ^ (4 * (r & 7)))) = v;
}

__global__ void transpose_pack_kernel(const float* __restrict__ in, float* __restrict__ out,
                                      int K, int N) {
    __shared__ float tsm[32][33];
    int k0 = blockIdx.y * 32, n0 = blockIdx.x * 32;
    int tx = threadIdx.x, ty = threadIdx.y;
#pragma unroll
    for (int i = 0; i < 32; i += 8)
        tsm[ty + i][tx] = in[(size_t)(k0 + ty + i) * N + n0 + tx];
    __syncthreads();
    int kk = gath8(tx);
    int tpr = K / 32;
#pragma unroll
    for (int i = 0; i < 32; i += 8) {
        int nr = n0 + ty + i;
        out[packaddr(nr, k0 + tx, tpr)] = rn_tf32(tsm[kk][ty + i]);
    }
}

// ---------------------------------------------------------------- tf32 GEMM
#define GBM 128
#define GBN 128
#define GBK 32
#define GSTG 3
#define TILE_B 16384
#define SM_B_OFF (GSTG * TILE_B)
#define SM_MBAR  (2 * GSTG * TILE_B)
#define GEMM_SMEM (SM_MBAR + 64)

__global__ __launch_bounds__(256, 2) void gemm_tf32(
    const float* __restrict__ A, const float* __restrict__ Bt,
    const float* __restrict__ bias, float* __restrict__ C,
    float* __restrict__ kp, float* __restrict__ vp,
    int M, int N, int K, int mode)
{
    extern __shared__ float smf[];
    const uint32_t smb = smem_u32(smf);
    const uint32_t mb = smb + SM_MBAR;

    const int tid = threadIdx.x, wid = tid >> 5, lane = tid & 31;
    const int g = lane >> 2, t = lane & 3;
    const int wm = wid & 3, wn = wid >> 2;
    const int m0 = blockIdx.y * GBM, n0 = blockIdx.x * GBN;
    const int NCH = K / GBK;

    if (tid == 0) {
        MBAR_INIT(mb + 0, 1); MBAR_INIT(mb + 8, 1); MBAR_INIT(mb + 16, 1);
    }
    __syncthreads();

    const float* a_src = A  + ((size_t)(m0 >> 7) * NCH) * 4096;
    const float* b_src = Bt + ((size_t)(n0 >> 7) * NCH) * 4096;

    if (tid == 0) {
#pragma unroll
        for (int s = 0; s < GSTG - 1; s++) {
            MBAR_EXPECT(mb + 8 * s, 2 * TILE_B);
            CP_BULK(smb + s * TILE_B,            a_src + s * 4096, TILE_B, mb + 8 * s);
            CP_BULK(smb + SM_B_OFF + s * TILE_B, b_src + s * 4096, TILE_B, mb + 8 * s);
        }
    }

    const int lq = lane >> 3, li = lane & 7;
    const uint32_t sw4 = 4u * (uint32_t)li;
    const uint32_t ko  = (uint32_t)((lq >> 1) * 4);
    uint32_t a_rb[2], b_rb[4];
#pragma unroll
    for (int mt = 0; mt < 2; mt++)
        a_rb[mt] = (uint32_t)(wm * 32 + mt * 16 + (lq & 1) * 8 + li) * 128u;
#pragma unroll
    for (int p = 0; p < 4; p++)
        b_rb[p] = (uint32_t)(wn * 64 + p * 16 + (lq & 1) * 8 + li) * 128u;

    float acc[2][8][4];
#pragma unroll
    for (int mt = 0; mt < 2; mt++)
#pragma unroll
        for (int nt = 0; nt < 8; nt++)
#pragma unroll
            for (int k = 0; k < 4; k++) acc[mt][nt][k] = 0.f;

    int s_use = 0, ph = 0, s_fill = GSTG - 1;
    for (int kb = 0; kb < NCH; kb++) {
        MBAR_WAIT(mb + 8 * s_use, ph);
        __syncthreads();

        if (kb + GSTG - 1 < NCH && tid == 0) {
            MBAR_EXPECT(mb + 8 * s_fill, 2 * TILE_B);
            CP_BULK(smb + s_fill * TILE_B,            a_src + (kb + GSTG - 1) * 4096,
                    TILE_B, mb + 8 * s_fill);
            CP_BULK(smb + SM_B_OFF + s_fill * TILE_B, b_src + (kb + GSTG - 1) * 4096,
                    TILE_B, mb + 8 * s_fill);
        }

        const uint32_t asb = smb + s_use * TILE_B;
        const uint32_t bsb = smb + SM_B_OFF + s_use * TILE_B;
#pragma unroll
        for (int ks = 0; ks < 4; ks++) {
            const uint32_t kx = (((uint32_t)(ks * 8) + ko) ^ sw4) * 4u;
            uint32_t af[2][4], bf[8][2], bt4[4];
            ldsm_x4(af[0], asb + a_rb[0] + kx);
            ldsm_x4(af[1], asb + a_rb[1] + kx);
#pragma unroll
            for (int p = 0; p < 4; p++) {
                ldsm_x4(bt4, bsb + b_rb[p] + kx);
                bf[2 * p][0]     = bt4[0];
                bf[2 * p + 1][0] = bt4[1];
                bf[2 * p][1]     = bt4[2];
                bf[2 * p + 1][1] = bt4[3];
            }
#pragma unroll
            for (int mt = 0; mt < 2; mt++)
#pragma unroll
                for (int nt = 0; nt < 8; nt++)
                    mma_tf32(acc[mt][nt], af[mt], bf[nt]);
        }
        if (++s_fill == GSTG) s_fill = 0;
        if (++s_use == GSTG) { s_use = 0; ph ^= 1; }
    }

    // epilogue
#pragma unroll
    for (int mt = 0; mt < 2; mt++) {
        int r0 = m0 + wm * 32 + mt * 16 + g;
#pragma unroll
        for (int nt = 0; nt < 8; nt++) {
            int c = n0 + wn * 64 + nt * 8 + 2 * t;
            float2 b2 = *(const float2*)(bias + c);
            float2 v0 = make_float2(acc[mt][nt][0] + b2.x, acc[mt][nt][1] + b2.y);
            float2 v1 = make_float2(acc[mt][nt][2] + b2.x, acc[mt][nt][3] + b2.y);
            if (mode == 1) {
                v0.x = rn_tf32(v0.x); v0.y = rn_tf32(v0.y);
                v1.x = rn_tf32(v1.x); v1.y = rn_tf32(v1.y);
                int b0 = r0 >> 11;
                int tok = r0 & 2047;
                if (c < 1024) {
                    // Q: col-permute within 8-groups into qkv
                    int c0p = (c & ~7) | perm8(c & 7);
                    int c1p = (c & ~7) | perm8((c & 7) + 1);
                    C[(size_t)r0 * N + c0p] = v0.x;
                    C[(size_t)r0 * N + c1p] = v0.y;
                    C[(size_t)(r0 + 8) * N + c0p] = v1.x;
                    C[(size_t)(r0 + 8) * N + c1p] = v1.y;
                } else if (c < 2048) {
                    // K -> packed tile [tok][d-perm], swizzled (smem image)
                    int h = (c - 1024) >> 6, d0 = (c - 1024) & 63;
                    int dp0 = (d0 & ~7) | perm8(d0 & 7);
                    int dp1 = (d0 & ~7) | perm8((d0 & 7) + 1);
                    size_t tile = ((size_t)(b0 * NH + h) * 32 + (tok >> 6)) * 4096;
                    int ra = tok & 63, rb = ra + 8;
                    kp[tile + swz64(ra, dp0)] = v0.x;
                    kp[tile + swz64(ra, dp1)] = v0.y;
                    kp[tile + swz64(rb, dp0)] = v1.x;
                    kp[tile + swz64(rb, dp1)] = v1.y;
                } else {
                    // V -> packed tile [d][tok-posv], swizzled (smem image)
                    int h = (c - 2048) >> 6, d0 = (c - 2048) & 63;
                    size_t tile = ((size_t)(b0 * NH + h) * 32 + (tok >> 6)) * 4096;
                    int tc0 = ((tok & 63) & ~7) | posv(tok & 7);
                    int tc1 = tc0 + 8;                 // (tok+8): same posv, +8 group
                    vp[tile + swz64(d0,     tc0)] = v0.x;
                    vp[tile + swz64(d0 + 1, tc0)] = v0.y;
                    vp[tile + swz64(d0,     tc1)] = v1.x;
                    vp[tile + swz64(d0 + 1, tc1)] = v1.y;
                }
            } else {
                *(float2*)(C + (size_t)r0 * N + c) = v0;
                *(float2*)(C + (size_t)(r0 + 8) * N + c) = v1;
            }
        }
    }
}

// ---------------------------------------------------------------- attention
// K/V staged via cp.async.bulk from pre-packed tiles (1 x 16KB each).
#define AQ 64
#define AK 64
#define SM_QS 0
#define SM_KS 4096
#define SM_VS (SM_KS + 2*4096)
#define SM_AMBAR ((SM_VS + 2*4096) * 4)      // 81920
#define ATTN_SMEM (SM_AMBAR + 64)

__global__ __launch_bounds__(128, 2) void attn_tc(const float* __restrict__ qkv,
                                                  const float* __restrict__ kp,
                                                  const float* __restrict__ vp,
                                                  float* __restrict__ y)
{
    extern __shared__ float sm[];
    const int tid = threadIdx.x;
    const int wid = tid >> 5, lane = tid & 31;
    const int g = lane >> 2, t = lane & 3;
    const int qt = gridDim.x - 1 - blockIdx.x;
    const int h  = blockIdx.y;
    const int b  = blockIdx.z;
    const int q0 = qt * AQ;
    const int r0 = wid * 16 + g;
    const uint32_t smb = smem_u32(sm);
    const uint32_t mb  = smb + SM_AMBAR;

    const int lq = lane >> 3, li = lane & 7;
    const uint32_t sw4 = 4u * (uint32_t)li;
    const uint32_t ko  = (uint32_t)((lq >> 1) * 4);
    const uint32_t rq  = (uint32_t)((lq & 1) * 8 + li);
    const uint32_t q_rb = (uint32_t)(wid * 16 + rq) * 256u;
    uint32_t n_rb[4];
#pragma unroll
    for (int p = 0; p < 4; p++) n_rb[p] = (uint32_t)(p * 16 + rq) * 256u;

    const float* kpb = kp + ((size_t)(b * NH + h) * 32) * 4096;
    const float* vpb = vp + ((size_t)(b * NH + h) * 32) * 4096;

    if (tid == 0) { MBAR_INIT(mb + 0, 1); MBAR_INIT(mb + 8, 1); }

    // stage Q (scaled, swizzled)
    {
        const float* qbase = qkv + ((size_t)(b * TT + q0)) * C3 + h * HD;
#pragma unroll
        for (int i = 0; i < 8; i++) {
            int idx = tid + i * 128, row = idx >> 4, c4 = idx & 15;
            float4 v = *(const float4*)(qbase + (size_t)row * C3 + c4 * 4);
            v.x *= SCALE; v.y *= SCALE; v.z *= SCALE; v.w *= SCALE;
            *(float4*)(&sm[SM_QS + row * 64 + ((c4 * 4) ^ (4 * (row & 7)))]) = v;
        }
    }
    // prologue K/V tile 0 via bulk
    if (tid == 0) {
        MBAR_EXPECT(mb + 0, 2 * 16384);
        CP_BULK(smb + SM_KS * 4, kpb, 16384, mb + 0);
        CP_BULK(smb + SM_VS * 4, vpb, 16384, mb + 0);
    }
    __syncthreads();

    uint32_t qf[8][4];
#pragma unroll
    for (int ds = 0; ds < 8; ds++)
        ldsm_x4(qf[ds], smb + SM_QS * 4 + q_rb + ((((uint32_t)(ds * 8) + ko) ^ sw4) << 2));

    float oacc[8][4];
#pragma unroll
    for (int nt = 0; nt < 8; nt++)
#pragma unroll
        for (int k = 0; k < 4; k++) oacc[nt][k] = 0.f;
    float mrow0 = -INFINITY, mrow1 = -INFINITY, lrow0 = 0.f, lrow1 = 0.f;

    const int pp0 = perm8(2 * t), pp1 = perm8(2 * t + 1);

    for (int kt = 0; kt <= qt; kt++) {
        const int buf = kt & 1;
        MBAR_WAIT(mb + 8 * buf, (kt >> 1) & 1);
        __syncthreads();
        if (kt < qt && tid == 0) {
            MBAR_EXPECT(mb + 8 * (buf ^ 1), 2 * 16384);
            CP_BULK(smb + (SM_KS + (buf ^ 1) * 4096) * 4, kpb + (size_t)(kt + 1) * 4096,
                    16384, mb + 8 * (buf ^ 1));
            CP_BULK(smb + (SM_VS + (buf ^ 1) * 4096) * 4, vpb + (size_t)(kt + 1) * 4096,
                    16384, mb + 8 * (buf ^ 1));
        }

        const uint32_t ksb = smb + (SM_KS + buf * 4096) * 4;
        const uint32_t vsb = smb + (SM_VS + buf * 4096) * 4;

        // S = Q K^T
        float sacc[8][4];
#pragma unroll
        for (int nt = 0; nt < 8; nt++)
#pragma unroll
            for (int k = 0; k < 4; k++) sacc[nt][k] = 0.f;
#pragma unroll
        for (int ds = 0; ds < 8; ds++) {
            const uint32_t kx = (((uint32_t)(ds * 8) + ko) ^ sw4) << 2;
            uint32_t bf[8][2], bt4[4];
#pragma unroll
            for (int p = 0; p < 4; p++) {
                ldsm_x4(bt4, ksb + n_rb[p] + kx);
                bf[2 * p][0]     = bt4[0];
                bf[2 * p + 1][0] = bt4[1];
                bf[2 * p][1]     = bt4[2];
                bf[2 * p + 1][1] = bt4[3];
            }
#pragma unroll
            for (int nt = 0; nt < 8; nt++)
                mma_tf32(sacc[nt], qf[ds], bf[nt]);
        }

        if (kt == qt) {
#pragma unroll
            for (int nt = 0; nt < 8; nt++) {
                int c = nt * 8 + 2 * t;
                if (c     > r0)     sacc[nt][0] = -1e30f;
                if (c + 1 > r0)     sacc[nt][1] = -1e30f;
                if (c     > r0 + 8) sacc[nt][2] = -1e30f;
                if (c + 1 > r0 + 8) sacc[nt][3] = -1e30f;
            }
        }

        // online softmax
        float tm0 = -INFINITY, tm1 = -INFINITY;
#pragma unroll
        for (int nt = 0; nt < 8; nt++) {
            tm0 = fmaxf(tm0, fmaxf(sacc[nt][0], sacc[nt][1]));
            tm1 = fmaxf(tm1, fmaxf(sacc[nt][2], sacc[nt][3]));
        }
        tm0 = fmaxf(tm0, __shfl_xor_sync(0xffffffffu, tm0, 1));
        tm0 = fmaxf(tm0, __shfl_xor_sync(0xffffffffu, tm0, 2));
        tm1 = fmaxf(tm1, __shfl_xor_sync(0xffffffffu, tm1, 1));
        tm1 = fmaxf(tm1, __shfl_xor_sync(0xffffffffu, tm1, 2));
        float m0 = fmaxf(mrow0, tm0), m1 = fmaxf(mrow1, tm1);
        float a0 = __expf(mrow0 - m0), a1 = __expf(mrow1 - m1);
        mrow0 = m0; mrow1 = m1;
        float rs0 = 0.f, rs1 = 0.f;
#pragma unroll
        for (int nt = 0; nt < 8; nt++) {
            sacc[nt][0] = __expf(sacc[nt][0] - m0); rs0 += sacc[nt][0];
            sacc[nt][1] = __expf(sacc[nt][1] - m0); rs0 += sacc[nt][1];
            sacc[nt][2] = __expf(sacc[nt][2] - m1); rs1 += sacc[nt][2];
            sacc[nt][3] = __expf(sacc[nt][3] - m1); rs1 += sacc[nt][3];
        }
        rs0 += __shfl_xor_sync(0xffffffffu, rs0, 1);
        rs0 += __shfl_xor_sync(0xffffffffu, rs0, 2);
        rs1 += __shfl_xor_sync(0xffffffffu, rs1, 1);
        rs1 += __shfl_xor_sync(0xffffffffu, rs1, 2);
        lrow0 = lrow0 * a0 + rs0;
        lrow1 = lrow1 * a1 + rs1;
#pragma unroll
        for (int nt = 0; nt < 8; nt++) {
            oacc[nt][0] *= a0; oacc[nt][1] *= a0;
            oacc[nt][2] *= a1; oacc[nt][3] *= a1;
        }

        // O += P @ V — P from sacc registers ([c0,c2,c1,c3], pos_v V tokens)
#pragma unroll
        for (int kk = 0; kk < 8; kk++) {
            const uint32_t kx = (((uint32_t)(kk * 8) + ko) ^ sw4) << 2;
            uint32_t af[4], bf[8][2], bt4[4];
            af[0] = __float_as_uint(rn_tf32(sacc[kk][0]));
            af[1] = __float_as_uint(rn_tf32(sacc[kk][2]));
            af[2] = __float_as_uint(rn_tf32(sacc[kk][1]));
            af[3] = __float_as_uint(rn_tf32(sacc[kk][3]));
#pragma unroll
            for (int p = 0; p < 4; p++) {
                ldsm_x4(bt4, vsb + n_rb[p] + kx);
                bf[2 * p][0]     = bt4[0];
                bf[2 * p + 1][0] = bt4[1];
                bf[2 * p][1]     = bt4[2];
                bf[2 * p + 1][1] = bt4[3];
            }
#pragma unroll
            for (int nt = 0; nt < 8; nt++)
                mma_tf32(oacc[nt], af, bf[nt]);
        }
    }

    // normalize + store into PACKED y (proj GEMM's A)
    float inv0 = 1.0f / lrow0, inv1 = 1.0f / lrow1;
    const int row0 = b * TT + q0 + r0;
    const int row1 = row0 + 8;
#pragma unroll
    for (int nt = 0; nt < 8; nt++) {
        int c0 = h * HD + nt * 8 + pp0;
        int c1 = h * HD + nt * 8 + pp1;
        y[packaddr(row0, c0, 32)] = rn_tf32(oacc[nt][0] * inv0);
        y[packaddr(row0, c1, 32)] = rn_tf32(oacc[nt][1] * inv0);
        y[packaddr(row1, c0, 32)] = rn_tf32(oacc[nt][2] * inv1);
        y[packaddr(row1, c1, 32)] = rn_tf32(oacc[nt][3] * inv1);
    }
}

// ---------------------------------------------------------------- launch
extern "C" void kernel_launch(void* const* d_in, const int* in_sizes, int n_in,
                              void* d_out, int out_size)
{
    const float* x      = (const float*)d_in[0];
    const float* w_attn = (const float*)d_in[1];
    const float* b_attn = (const float*)d_in[2];
    const float* w_proj = (const float*)d_in[3];
    const float* b_proj = (const float*)d_in[4];
    float* out = (float*)d_out;

    float *qkv, *kp, *vp, *yb, *xp, *waT, *wpT;
    cudaGetSymbolAddress((void**)&qkv, g_qkv);
    cudaGetSymbolAddress((void**)&kp,  g_kp);
    cudaGetSymbolAddress((void**)&vp,  g_vp);
    cudaGetSymbolAddress((void**)&yb,  g_y);
    cudaGetSymbolAddress((void**)&xp,  g_xp);
    cudaGetSymbolAddress((void**)&waT, g_waT);
    cudaGetSymbolAddress((void**)&wpT, g_wpT);

    cudaFuncSetAttribute(gemm_tf32, cudaFuncAttributeMaxDynamicSharedMemorySize, GEMM_SMEM);
    cudaFuncSetAttribute(attn_tc,   cudaFuncAttributeMaxDynamicSharedMemorySize, ATTN_SMEM);

    // 0) pack operands
    pack_a_kernel<<<(BT * CC / 4) / 256, 256>>>(x, xp, CC);
    transpose_pack_kernel<<<dim3(C3 / 32, CC / 32), dim3(32, 8)>>>(w_attn, waT, CC, C3);
    transpose_pack_kernel<<<dim3(CC / 32, CC / 32), dim3(32, 8)>>>(w_proj, wpT, CC, CC);

    // 1) QKV GEMM (Q -> qkv permuted; K,V -> packed smem-image tiles)
    gemm_tf32<<<dim3(C3 / GBN, BT / GBM), 256, GEMM_SMEM>>>(xp, waT, b_attn, qkv, kp, vp,
                                                            BT, C3, CC, 1);

    // 2) causal attention (bulk-staged K/V tiles; writes packed y)
    attn_tc<<<dim3(TT / AQ, NH, BB), 128, ATTN_SMEM>>>(qkv, kp, vp, yb);

    // 3) out = y @ w_proj + b_proj
    gemm_tf32<<<dim3(CC / GBN, BT / GBM), 256, GEMM_SMEM>>>(yb, wpT, b_proj, out, kp, vp,
                                                            BT, CC, CC, 0);
}